// round 2
// baseline (speedup 1.0000x reference)
#include <cuda_runtime.h>
#include <math.h>

// Problem constants
static constexpr int Bc   = 2;
static constexpr int Sc   = 2048;
static constexpr int Dc   = 768;
static constexpr int Hc   = 12;
static constexpr int DKc  = 64;
static constexpr int DFFc = 3072;
static constexpr int Mc   = Bc * Sc;   // 4096 rows

// Scratch (static device globals: allocation-free)
__device__ float g_q  [Mc * Dc];
__device__ float g_k  [Mc * Dc];
__device__ float g_v  [Mc * Dc];
__device__ float g_ctx[Mc * Dc];
__device__ float g_tmp[Mc * Dc];
__device__ float g_x1 [Mc * Dc];
__device__ float g_ff1[Mc * DFFc];

// ---------------------------------------------------------------------------
// SGEMM: C[M,N] = A[M,K] @ W[K,N] + bias[N]   (EPI==1: ReLU)
// BM=BN=128, BK=16, 256 threads, 8x8 per-thread microtile
// ---------------------------------------------------------------------------
template<int EPI>
__global__ __launch_bounds__(256)
void sgemm_kernel(const float* __restrict__ A, const float* __restrict__ W,
                  const float* __restrict__ bias, float* __restrict__ C,
                  int Mdim, int Ndim, int Kdim)
{
    __shared__ float As[16][128];
    __shared__ float Bs[16][128];

    const int tid  = threadIdx.x;
    const int bx   = blockIdx.x;   // N tiles
    const int by   = blockIdx.y;   // M tiles
    const int tcol = tid & 15;
    const int trow = tid >> 4;

    float acc[8][8] = {};

    const float* Ap = A + (size_t)by * 128 * Kdim;
    const float* Wp = W + bx * 128;

    const int ar = tid >> 2;           // 0..63
    const int ac = (tid & 3) << 2;     // 0,4,8,12
    const int br = tid >> 5;           // 0..7
    const int bc = (tid & 31) << 2;    // 0..124

    for (int k0 = 0; k0 < Kdim; k0 += 16) {
        float4 a0 = *(const float4*)(Ap + (size_t)ar        * Kdim + k0 + ac);
        float4 a1 = *(const float4*)(Ap + (size_t)(ar + 64) * Kdim + k0 + ac);
        float4 b0 = *(const float4*)(Wp + (size_t)(k0 + br)     * Ndim + bc);
        float4 b1 = *(const float4*)(Wp + (size_t)(k0 + br + 8) * Ndim + bc);

        As[ac + 0][ar] = a0.x; As[ac + 1][ar] = a0.y;
        As[ac + 2][ar] = a0.z; As[ac + 3][ar] = a0.w;
        As[ac + 0][ar + 64] = a1.x; As[ac + 1][ar + 64] = a1.y;
        As[ac + 2][ar + 64] = a1.z; As[ac + 3][ar + 64] = a1.w;
        *(float4*)&Bs[br][bc]     = b0;
        *(float4*)&Bs[br + 8][bc] = b1;
        __syncthreads();

        #pragma unroll
        for (int kk = 0; kk < 16; kk++) {
            float areg[8], breg[8];
            #pragma unroll
            for (int i = 0; i < 8; i++) areg[i] = As[kk][trow * 8 + i];
            #pragma unroll
            for (int j = 0; j < 8; j++) breg[j] = Bs[kk][tcol * 8 + j];
            #pragma unroll
            for (int i = 0; i < 8; i++)
                #pragma unroll
                for (int j = 0; j < 8; j++)
                    acc[i][j] += areg[i] * breg[j];
        }
        __syncthreads();
    }

    const int crow = by * 128 + trow * 8;
    const int ccol = bx * 128 + tcol * 8;
    #pragma unroll
    for (int i = 0; i < 8; i++) {
        #pragma unroll
        for (int j = 0; j < 8; j++) {
            float vv = acc[i][j] + bias[ccol + j];
            if (EPI == 1) vv = fmaxf(vv, 0.f);
            acc[i][j] = vv;
        }
        *(float4*)&C[(size_t)(crow + i) * Ndim + ccol] =
            make_float4(acc[i][0], acc[i][1], acc[i][2], acc[i][3]);
        *(float4*)&C[(size_t)(crow + i) * Ndim + ccol + 4] =
            make_float4(acc[i][4], acc[i][5], acc[i][6], acc[i][7]);
    }
}

// ---------------------------------------------------------------------------
// Flash attention per (b,h): Q tile 64, K tile 32, online softmax, mask fused.
// grid = (S/64, B*H), 256 threads.
// ---------------------------------------------------------------------------
__global__ __launch_bounds__(256)
void attn_kernel(const float* __restrict__ Q, const float* __restrict__ K,
                 const float* __restrict__ V, const int* __restrict__ mask,
                 float* __restrict__ ctx)
{
    constexpr int QT = 64, KT = 32;
    __shared__ float Qs[QT][DKc];        // 16 KB
    __shared__ float KVs[KT][DKc + 1];   // 8.1 KB (K tile, then V tile)
    __shared__ float Ss[QT][KT + 1];     // 8.25 KB (scores -> P)
    __shared__ float m_sh[QT], l_sh[QT], a_sh[QT];

    const int tid = threadIdx.x;
    const int qb  = blockIdx.x;
    const int bh  = blockIdx.y;
    const int b   = bh / Hc;
    const int h   = bh - b * Hc;
    const int q0  = qb * QT;
    const int rb  = b * Sc;     // row base into [B*S, D]
    const int c0  = h * DKc;    // head column offset

    // Load Q tile (vectorized)
    for (int i = tid; i < QT * DKc / 4; i += 256) {
        int r = i >> 4, c = (i & 15) << 2;
        *(float4*)&Qs[r][c] = *(const float4*)&Q[(size_t)(rb + q0 + r) * Dc + c0 + c];
    }
    if (tid < QT) { m_sh[tid] = -INFINITY; l_sh[tid] = 0.f; }
    __syncthreads();

    const int ty = tid >> 4, tx = tid & 15;
    float oacc[4][4] = {};

    for (int k0 = 0; k0 < Sc; k0 += KT) {
        // Load K tile
        for (int i = tid; i < KT * DKc; i += 256) {
            int r = i >> 6, c = i & 63;
            KVs[r][c] = K[(size_t)(rb + k0 + r) * Dc + c0 + c];
        }
        __syncthreads();

        // S = Q K^T (64x32); thread covers rows ty*4+i, cols tx*2+j
        float sacc[4][2] = {};
        #pragma unroll 8
        for (int d = 0; d < DKc; d++) {
            float qv[4], kv[2];
            #pragma unroll
            for (int i = 0; i < 4; i++) qv[i] = Qs[ty * 4 + i][d];
            kv[0] = KVs[tx * 2][d];
            kv[1] = KVs[tx * 2 + 1][d];
            #pragma unroll
            for (int i = 0; i < 4; i++) {
                sacc[i][0] += qv[i] * kv[0];
                sacc[i][1] += qv[i] * kv[1];
            }
        }
        // Scale + mask, write to Ss
        #pragma unroll
        for (int i = 0; i < 4; i++) {
            int r = ty * 4 + i;
            #pragma unroll
            for (int j = 0; j < 2; j++) {
                int c = tx * 2 + j;
                int mv = mask[(size_t)(q0 + r) * Sc + k0 + c];
                Ss[r][c] = (mv == 0) ? -1e9f : sacc[i][j] * 0.125f;
            }
        }
        __syncthreads();

        // Load V (overwrites K in KVs); threads<64 also do the online softmax
        for (int i = tid; i < KT * DKc; i += 256) {
            int r = i >> 6, c = i & 63;
            KVs[r][c] = V[(size_t)(rb + k0 + r) * Dc + c0 + c];
        }
        if (tid < QT) {
            float mold = m_sh[tid];
            float mx = mold;
            #pragma unroll 8
            for (int c = 0; c < KT; c++) mx = fmaxf(mx, Ss[tid][c]);
            float alpha = __expf(mold - mx);   // first iter: exp(-inf)=0
            float sum = 0.f;
            #pragma unroll 8
            for (int c = 0; c < KT; c++) {
                float p = __expf(Ss[tid][c] - mx);
                Ss[tid][c] = p;
                sum += p;
            }
            l_sh[tid] = l_sh[tid] * alpha + sum;
            m_sh[tid] = mx;
            a_sh[tid] = alpha;
        }
        __syncthreads();

        // Rescale O, then O += P @ V (thread covers rows ty*4+i, cols tx*4+j)
        float al[4];
        #pragma unroll
        for (int i = 0; i < 4; i++) al[i] = a_sh[ty * 4 + i];
        #pragma unroll
        for (int i = 0; i < 4; i++)
            #pragma unroll
            for (int j = 0; j < 4; j++) oacc[i][j] *= al[i];

        #pragma unroll 8
        for (int k = 0; k < KT; k++) {
            float pv[4], vv[4];
            #pragma unroll
            for (int i = 0; i < 4; i++) pv[i] = Ss[ty * 4 + i][k];
            #pragma unroll
            for (int j = 0; j < 4; j++) vv[j] = KVs[k][tx * 4 + j];
            #pragma unroll
            for (int i = 0; i < 4; i++)
                #pragma unroll
                for (int j = 0; j < 4; j++) oacc[i][j] += pv[i] * vv[j];
        }
        __syncthreads();
    }

    float inv[4];
    #pragma unroll
    for (int i = 0; i < 4; i++) inv[i] = 1.f / l_sh[ty * 4 + i];
    #pragma unroll
    for (int i = 0; i < 4; i++)
        #pragma unroll
        for (int j = 0; j < 4; j++)
            ctx[(size_t)(rb + q0 + ty * 4 + i) * Dc + c0 + tx * 4 + j] = oacc[i][j] * inv[i];
}

// ---------------------------------------------------------------------------
// out = alpha * ((x+y) - mean) / (std_unbiased + eps) + beta, per row of 768
// grid = 4096 rows, 256 threads (3 elems/thread)
// ---------------------------------------------------------------------------
__global__ __launch_bounds__(256)
void add_ln_kernel(const float* __restrict__ x, const float* __restrict__ y,
                   const float* __restrict__ alpha, const float* __restrict__ beta,
                   float* __restrict__ out)
{
    const int row = blockIdx.x;
    const int tid = threadIdx.x;
    const float* xr = x + (size_t)row * Dc;
    const float* yr = y + (size_t)row * Dc;

    __shared__ float red[8];
    __shared__ float sm_mean, sm_scale;

    float v[3];
    float s = 0.f;
    #pragma unroll
    for (int t = 0; t < 3; t++) {
        v[t] = xr[tid + 256 * t] + yr[tid + 256 * t];
        s += v[t];
    }
    #pragma unroll
    for (int o = 16; o > 0; o >>= 1) s += __shfl_xor_sync(0xFFFFFFFFu, s, o);
    if ((tid & 31) == 0) red[tid >> 5] = s;
    __syncthreads();
    if (tid == 0) {
        float tot = 0.f;
        #pragma unroll
        for (int w = 0; w < 8; w++) tot += red[w];
        sm_mean = tot * (1.0f / (float)Dc);
    }
    __syncthreads();
    const float mean = sm_mean;

    float sq = 0.f;
    #pragma unroll
    for (int t = 0; t < 3; t++) {
        float d = v[t] - mean;
        sq += d * d;
    }
    #pragma unroll
    for (int o = 16; o > 0; o >>= 1) sq += __shfl_xor_sync(0xFFFFFFFFu, sq, o);
    if ((tid & 31) == 0) red[tid >> 5] = sq;
    __syncthreads();
    if (tid == 0) {
        float tot = 0.f;
        #pragma unroll
        for (int w = 0; w < 8; w++) tot += red[w];
        float var = tot * (1.0f / (float)(Dc - 1));   // unbiased (ddof=1)
        sm_scale = 1.0f / (sqrtf(var) + 1e-6f);       // eps added to std
    }
    __syncthreads();

    const float sc = sm_scale * alpha[0];
    const float bt = beta[0];
    #pragma unroll
    for (int t = 0; t < 3; t++)
        out[(size_t)row * Dc + tid + 256 * t] = (v[t] - mean) * sc + bt;
}

// ---------------------------------------------------------------------------
extern "C" void kernel_launch(void* const* d_in, const int* in_sizes, int n_in,
                              void* d_out, int out_size)
{
    const float* x      = (const float*)d_in[0];
    const float* wq     = (const float*)d_in[1];
    const float* bq     = (const float*)d_in[2];
    const float* wk     = (const float*)d_in[3];
    const float* bk     = (const float*)d_in[4];
    const float* wv     = (const float*)d_in[5];
    const float* bv     = (const float*)d_in[6];
    const float* wo     = (const float*)d_in[7];
    const float* bo     = (const float*)d_in[8];
    const float* w1     = (const float*)d_in[9];
    const float* b1     = (const float*)d_in[10];
    const float* w2     = (const float*)d_in[11];
    const float* b2     = (const float*)d_in[12];
    const float* alpha1 = (const float*)d_in[13];
    const float* beta1  = (const float*)d_in[14];
    const float* alpha2 = (const float*)d_in[15];
    const float* beta2  = (const float*)d_in[16];
    const int*   mask   = (const int*)d_in[17];

    float *q, *k, *v, *ctx, *tmp, *x1, *ff1;
    cudaGetSymbolAddress((void**)&q,   g_q);
    cudaGetSymbolAddress((void**)&k,   g_k);
    cudaGetSymbolAddress((void**)&v,   g_v);
    cudaGetSymbolAddress((void**)&ctx, g_ctx);
    cudaGetSymbolAddress((void**)&tmp, g_tmp);
    cudaGetSymbolAddress((void**)&x1,  g_x1);
    cudaGetSymbolAddress((void**)&ff1, g_ff1);

    dim3 blk(256);
    dim3 gD(Dc / 128, Mc / 128);     // (6, 32)
    dim3 gF(DFFc / 128, Mc / 128);   // (24, 32)

    // QKV projections
    sgemm_kernel<0><<<gD, blk>>>(x, wq, bq, q, Mc, Dc, Dc);
    sgemm_kernel<0><<<gD, blk>>>(x, wk, bk, k, Mc, Dc, Dc);
    sgemm_kernel<0><<<gD, blk>>>(x, wv, bv, v, Mc, Dc, Dc);

    // Fused flash attention (mask + softmax + PV)
    attn_kernel<<<dim3(Sc / 64, Bc * Hc), blk>>>(q, k, v, mask, ctx);

    // Output projection, residual + LN1
    sgemm_kernel<0><<<gD, blk>>>(ctx, wo, bo, tmp, Mc, Dc, Dc);
    add_ln_kernel<<<Mc, blk>>>(x, tmp, alpha1, beta1, x1);

    // FFN
    sgemm_kernel<1><<<gF, blk>>>(x1, w1, b1, ff1, Mc, DFFc, Dc);
    sgemm_kernel<0><<<gD, blk>>>(ff1, w2, b2, tmp, Mc, Dc, DFFc);
    add_ln_kernel<<<Mc, blk>>>(x1, tmp, alpha2, beta2, (float*)d_out);
}

// round 3
// speedup vs baseline: 1.5019x; 1.5019x over previous
#include <cuda_runtime.h>
#include <cuda_bf16.h>
#include <stdint.h>
#include <math.h>

// Problem constants
static constexpr int Bc   = 2;
static constexpr int Sc   = 2048;
static constexpr int Dc   = 768;
static constexpr int Hc   = 12;
static constexpr int DKc  = 64;
static constexpr int DFFc = 3072;
static constexpr int Mc   = Bc * Sc;   // 4096 rows

// Scratch (static device globals: allocation-free)
__device__ float g_q  [Mc * Dc];
__device__ float g_k  [Mc * Dc];
__device__ float g_v  [Mc * Dc];
__device__ float g_ctx[Mc * Dc];
__device__ float g_tmp[Mc * Dc];
__device__ float g_x1 [Mc * Dc];
__device__ float g_ff1[Mc * DFFc];

// ---------------------------------------------------------------------------
// helpers
// ---------------------------------------------------------------------------
__device__ __forceinline__ uint32_t sptr(const void* p) {
    return (uint32_t)__cvta_generic_to_shared(p);
}

__device__ __forceinline__ void ldsm4(uint32_t r[4], uint32_t addr) {
    asm volatile("ldmatrix.sync.aligned.m8n8.x4.shared.b16 {%0,%1,%2,%3},[%4];"
                 : "=r"(r[0]), "=r"(r[1]), "=r"(r[2]), "=r"(r[3]) : "r"(addr));
}
__device__ __forceinline__ void ldsm4t(uint32_t r[4], uint32_t addr) {
    asm volatile("ldmatrix.sync.aligned.m8n8.x4.trans.shared.b16 {%0,%1,%2,%3},[%4];"
                 : "=r"(r[0]), "=r"(r[1]), "=r"(r[2]), "=r"(r[3]) : "r"(addr));
}
__device__ __forceinline__ void mma16816(float c[4], const uint32_t a[4],
                                         uint32_t b0, uint32_t b1) {
    asm volatile(
        "mma.sync.aligned.m16n8k16.row.col.f32.bf16.bf16.f32 "
        "{%0,%1,%2,%3},{%4,%5,%6,%7},{%8,%9},{%0,%1,%2,%3};"
        : "+f"(c[0]), "+f"(c[1]), "+f"(c[2]), "+f"(c[3])
        : "r"(a[0]), "r"(a[1]), "r"(a[2]), "r"(a[3]), "r"(b0), "r"(b1));
}

// convert 4 floats -> hi/lo bf16, store as 8B each
__device__ __forceinline__ void cvt4(float4 f, __nv_bfloat16* hp, __nv_bfloat16* lp) {
    float v[4] = {f.x, f.y, f.z, f.w};
    __nv_bfloat16 h[4], l[4];
#pragma unroll
    for (int i = 0; i < 4; i++) {
        h[i] = __float2bfloat16(v[i]);
        l[i] = __float2bfloat16(v[i] - __bfloat162float(h[i]));
    }
    *(uint2*)hp = *(uint2*)h;
    *(uint2*)lp = *(uint2*)l;
}

// ---------------------------------------------------------------------------
// Tensor-core GEMM: C[M,N] = A[M,K] @ W[K,N] + bias   (EPI==1: ReLU)
// bf16 3-split (AhWh + AhWl + AlWh), fp32 accum. BM=BN=128, BK=32, 8 warps.
// ---------------------------------------------------------------------------
template<int EPI>
__global__ __launch_bounds__(256, 1)
void mma_gemm(const float* __restrict__ A, const float* __restrict__ W,
              const float* __restrict__ bias, float* __restrict__ C,
              int Ndim, int Kdim)
{
    __shared__ __nv_bfloat16 Ah[128][40], Al[128][40];   // [m][k], pad->20 words/row
    __shared__ __nv_bfloat16 Wh[32][136], Wl[32][136];   // [k][n], pad->68 words/row

    const int tid  = threadIdx.x;
    const int lane = tid & 31;
    const int wid  = tid >> 5;
    const int wm   = (wid & 1) * 64;
    const int wn   = (wid >> 1) * 32;
    const int bM   = blockIdx.y * 128;
    const int bN   = blockIdx.x * 128;

    // global staging roles
    const int arow = tid >> 1;            // 0..127
    const int acol = (tid & 1) * 16;      // 0/16
    const int wrow = tid >> 3;            // 0..31 (k)
    const int wcol = (tid & 7) * 16;      // n base

    const float* Abase = A + (size_t)(bM + arow) * Kdim + acol;
    const float* Wbase = W + (size_t)wrow * Ndim + bN + wcol;
    const size_t WkStride = (size_t)32 * Ndim;

    float4 ra[4], rw[4];
    const int T = Kdim / 32;

#pragma unroll
    for (int j = 0; j < 4; j++) ra[j] = *(const float4*)(Abase + j * 4);
#pragma unroll
    for (int j = 0; j < 4; j++) rw[j] = *(const float4*)(Wbase + j * 4);

    float acc[4][4][4];
#pragma unroll
    for (int a = 0; a < 4; a++)
#pragma unroll
        for (int b = 0; b < 4; b++)
#pragma unroll
            for (int c = 0; c < 4; c++) acc[a][b][c] = 0.f;

    const int lr    = lane & 15;
    const int lc8   = (lane >> 4) * 8;
    const int brow  = (lane & 7) + ((lane >> 3) & 1) * 8;
    const int bcol8 = (lane >> 4) * 8;

    for (int t = 0; t < T; t++) {
        __syncthreads();
#pragma unroll
        for (int j = 0; j < 4; j++) cvt4(ra[j], &Ah[arow][acol + j * 4], &Al[arow][acol + j * 4]);
#pragma unroll
        for (int j = 0; j < 4; j++) cvt4(rw[j], &Wh[wrow][wcol + j * 4], &Wl[wrow][wcol + j * 4]);
        __syncthreads();

        if (t + 1 < T) {
            const float* Ap = Abase + (t + 1) * 32;
            const float* Wp = Wbase + (size_t)(t + 1) * WkStride;
#pragma unroll
            for (int j = 0; j < 4; j++) ra[j] = *(const float4*)(Ap + j * 4);
#pragma unroll
            for (int j = 0; j < 4; j++) rw[j] = *(const float4*)(Wp + j * 4);
        }

#pragma unroll
        for (int ks = 0; ks < 32; ks += 16) {
            uint32_t ah[4][4], alr[4][4];
#pragma unroll
            for (int mi = 0; mi < 4; mi++) {
                ldsm4(ah[mi],  sptr(&Ah[wm + mi * 16 + lr][ks + lc8]));
                ldsm4(alr[mi], sptr(&Al[wm + mi * 16 + lr][ks + lc8]));
            }
#pragma unroll
            for (int p = 0; p < 2; p++) {
                uint32_t bh[4], bl[4];
                ldsm4t(bh, sptr(&Wh[ks + brow][wn + p * 16 + bcol8]));
                ldsm4t(bl, sptr(&Wl[ks + brow][wn + p * 16 + bcol8]));
#pragma unroll
                for (int s = 0; s < 2; s++) {
                    const int ni = p * 2 + s;
#pragma unroll
                    for (int mi = 0; mi < 4; mi++) {
                        mma16816(acc[mi][ni], ah[mi],  bh[s * 2], bh[s * 2 + 1]);
                        mma16816(acc[mi][ni], ah[mi],  bl[s * 2], bl[s * 2 + 1]);
                        mma16816(acc[mi][ni], alr[mi], bh[s * 2], bh[s * 2 + 1]);
                    }
                }
            }
        }
    }

    // epilogue
    const int gr = lane >> 2, gc = (lane & 3) * 2;
#pragma unroll
    for (int mi = 0; mi < 4; mi++) {
#pragma unroll
        for (int ni = 0; ni < 4; ni++) {
            int row = bM + wm + mi * 16 + gr;
            int col = bN + wn + ni * 8 + gc;
            float b0 = bias[col], b1 = bias[col + 1];
            float v0 = acc[mi][ni][0] + b0, v1 = acc[mi][ni][1] + b1;
            float v2 = acc[mi][ni][2] + b0, v3 = acc[mi][ni][3] + b1;
            if (EPI) {
                v0 = fmaxf(v0, 0.f); v1 = fmaxf(v1, 0.f);
                v2 = fmaxf(v2, 0.f); v3 = fmaxf(v3, 0.f);
            }
            *(float2*)&C[(size_t)row * Ndim + col]       = make_float2(v0, v1);
            *(float2*)&C[(size_t)(row + 8) * Ndim + col] = make_float2(v2, v3);
        }
    }
}

// ---------------------------------------------------------------------------
// Flash attention: QT=64, KT=64, 256 threads, 4x4 thread tiles.
// K stored transposed [d][k]; V [k][c]; 1 LDS.128 + 4 bcast LDS per 16 FFMA.
// ---------------------------------------------------------------------------
struct AttnSmem {
    float Qs[64][68];
    float Kt[64][68];   // [d][k]
    float Vs[64][68];   // [k][c]
    float Ss[64][68];
    float m_sh[64], l_sh[64], a_sh[64];
};

__global__ __launch_bounds__(256, 2)
void attn_kernel(const float* __restrict__ Q, const float* __restrict__ K,
                 const float* __restrict__ V, const int* __restrict__ mask,
                 float* __restrict__ ctx)
{
    extern __shared__ char smem_raw[];
    AttnSmem& sm = *reinterpret_cast<AttnSmem*>(smem_raw);

    const int tid = threadIdx.x;
    const int qb  = blockIdx.x;
    const int bh  = blockIdx.y;
    const int b   = bh / Hc;
    const int h   = bh - b * Hc;
    const int q0  = qb * 64;
    const int rb  = b * Sc;
    const int c0  = h * DKc;

    const int lrow = tid >> 2;         // 0..63
    const int lcol = (tid & 3) * 16;   // d base

    {
        const float* src = Q + (size_t)(rb + q0 + lrow) * Dc + c0 + lcol;
#pragma unroll
        for (int j = 0; j < 4; j++)
            *(float4*)&sm.Qs[lrow][lcol + j * 4] = *(const float4*)(src + j * 4);
    }
    if (tid < 64) { sm.m_sh[tid] = -INFINITY; sm.l_sh[tid] = 0.f; }
    __syncthreads();

    const int ty = tid >> 4, tx = tid & 15;
    float oacc[4][4] = {};

    for (int k0 = 0; k0 < Sc; k0 += 64) {
        // load K transposed + V
        {
            const float* ksrc = K + (size_t)(rb + k0 + lrow) * Dc + c0 + lcol;
#pragma unroll
            for (int j = 0; j < 4; j++) {
                float4 f = *(const float4*)(ksrc + j * 4);
                sm.Kt[lcol + j * 4 + 0][lrow] = f.x;
                sm.Kt[lcol + j * 4 + 1][lrow] = f.y;
                sm.Kt[lcol + j * 4 + 2][lrow] = f.z;
                sm.Kt[lcol + j * 4 + 3][lrow] = f.w;
            }
            const float* vsrc = V + (size_t)(rb + k0 + lrow) * Dc + c0 + lcol;
#pragma unroll
            for (int j = 0; j < 4; j++)
                *(float4*)&sm.Vs[lrow][lcol + j * 4] = *(const float4*)(vsrc + j * 4);
        }
        __syncthreads();

        // scores: S = Q K^T
        float sacc[4][4] = {};
#pragma unroll 4
        for (int d = 0; d < 64; d++) {
            float4 kv = *(const float4*)&sm.Kt[d][tx * 4];
            float qv[4];
#pragma unroll
            for (int i = 0; i < 4; i++) qv[i] = sm.Qs[ty * 4 + i][d];
#pragma unroll
            for (int i = 0; i < 4; i++) {
                sacc[i][0] += qv[i] * kv.x; sacc[i][1] += qv[i] * kv.y;
                sacc[i][2] += qv[i] * kv.z; sacc[i][3] += qv[i] * kv.w;
            }
        }
#pragma unroll
        for (int i = 0; i < 4; i++) {
            int r = ty * 4 + i;
            int4 mv = *(const int4*)&mask[(size_t)(q0 + r) * Sc + k0 + tx * 4];
            sm.Ss[r][tx * 4 + 0] = (mv.x == 0) ? -1e9f : sacc[i][0] * 0.125f;
            sm.Ss[r][tx * 4 + 1] = (mv.y == 0) ? -1e9f : sacc[i][1] * 0.125f;
            sm.Ss[r][tx * 4 + 2] = (mv.z == 0) ? -1e9f : sacc[i][2] * 0.125f;
            sm.Ss[r][tx * 4 + 3] = (mv.w == 0) ? -1e9f : sacc[i][3] * 0.125f;
        }
        __syncthreads();

        // online softmax: 4 threads per row
        {
            int row = tid >> 2, sub = tid & 3;
            float mold = sm.m_sh[row];
            float mx = mold;
#pragma unroll
            for (int c = 0; c < 16; c++) mx = fmaxf(mx, sm.Ss[row][sub * 16 + c]);
            mx = fmaxf(mx, __shfl_xor_sync(0xffffffffu, mx, 1));
            mx = fmaxf(mx, __shfl_xor_sync(0xffffffffu, mx, 2));
            float sum = 0.f;
#pragma unroll
            for (int c = 0; c < 16; c++) {
                float p = __expf(sm.Ss[row][sub * 16 + c] - mx);
                sm.Ss[row][sub * 16 + c] = p;
                sum += p;
            }
            sum += __shfl_xor_sync(0xffffffffu, sum, 1);
            sum += __shfl_xor_sync(0xffffffffu, sum, 2);
            if (sub == 0) {
                float alpha = __expf(mold - mx);   // first iter: exp(-inf)=0
                sm.l_sh[row] = sm.l_sh[row] * alpha + sum;
                sm.m_sh[row] = mx;
                sm.a_sh[row] = alpha;
            }
        }
        __syncthreads();

        // O = O*alpha + P @ V
        float al[4];
#pragma unroll
        for (int i = 0; i < 4; i++) al[i] = sm.a_sh[ty * 4 + i];
#pragma unroll
        for (int i = 0; i < 4; i++)
#pragma unroll
            for (int j = 0; j < 4; j++) oacc[i][j] *= al[i];

#pragma unroll 4
        for (int k = 0; k < 64; k++) {
            float4 vv = *(const float4*)&sm.Vs[k][tx * 4];
            float pv[4];
#pragma unroll
            for (int i = 0; i < 4; i++) pv[i] = sm.Ss[ty * 4 + i][k];
#pragma unroll
            for (int i = 0; i < 4; i++) {
                oacc[i][0] += pv[i] * vv.x; oacc[i][1] += pv[i] * vv.y;
                oacc[i][2] += pv[i] * vv.z; oacc[i][3] += pv[i] * vv.w;
            }
        }
        __syncthreads();
    }

#pragma unroll
    for (int i = 0; i < 4; i++) {
        float inv = 1.f / sm.l_sh[ty * 4 + i];
        float4 o = make_float4(oacc[i][0] * inv, oacc[i][1] * inv,
                               oacc[i][2] * inv, oacc[i][3] * inv);
        *(float4*)&ctx[(size_t)(rb + q0 + ty * 4 + i) * Dc + c0 + tx * 4] = o;
    }
}

// ---------------------------------------------------------------------------
// out = alpha * ((x+y) - mean) / (std_unbiased + eps) + beta, row of 768
// ---------------------------------------------------------------------------
__global__ __launch_bounds__(256)
void add_ln_kernel(const float* __restrict__ x, const float* __restrict__ y,
                   const float* __restrict__ alpha, const float* __restrict__ beta,
                   float* __restrict__ out)
{
    const int row = blockIdx.x;
    const int tid = threadIdx.x;
    const float* xr = x + (size_t)row * Dc;
    const float* yr = y + (size_t)row * Dc;

    __shared__ float red[8];
    __shared__ float sm_mean, sm_scale;

    float v[3];
    float s = 0.f;
#pragma unroll
    for (int t = 0; t < 3; t++) {
        v[t] = xr[tid + 256 * t] + yr[tid + 256 * t];
        s += v[t];
    }
#pragma unroll
    for (int o = 16; o > 0; o >>= 1) s += __shfl_xor_sync(0xFFFFFFFFu, s, o);
    if ((tid & 31) == 0) red[tid >> 5] = s;
    __syncthreads();
    if (tid == 0) {
        float tot = 0.f;
#pragma unroll
        for (int w = 0; w < 8; w++) tot += red[w];
        sm_mean = tot * (1.0f / (float)Dc);
    }
    __syncthreads();
    const float mean = sm_mean;

    float sq = 0.f;
#pragma unroll
    for (int t = 0; t < 3; t++) {
        float d = v[t] - mean;
        sq += d * d;
    }
#pragma unroll
    for (int o = 16; o > 0; o >>= 1) sq += __shfl_xor_sync(0xFFFFFFFFu, sq, o);
    if ((tid & 31) == 0) red[tid >> 5] = sq;
    __syncthreads();
    if (tid == 0) {
        float tot = 0.f;
#pragma unroll
        for (int w = 0; w < 8; w++) tot += red[w];
        float var = tot * (1.0f / (float)(Dc - 1));
        sm_scale = 1.0f / (sqrtf(var) + 1e-6f);
    }
    __syncthreads();

    const float sc = sm_scale * alpha[0];
    const float bt = beta[0];
#pragma unroll
    for (int t = 0; t < 3; t++)
        out[(size_t)row * Dc + tid + 256 * t] = (v[t] - mean) * sc + bt;
}

// ---------------------------------------------------------------------------
extern "C" void kernel_launch(void* const* d_in, const int* in_sizes, int n_in,
                              void* d_out, int out_size)
{
    const float* x      = (const float*)d_in[0];
    const float* wq     = (const float*)d_in[1];
    const float* bq     = (const float*)d_in[2];
    const float* wk     = (const float*)d_in[3];
    const float* bk     = (const float*)d_in[4];
    const float* wv     = (const float*)d_in[5];
    const float* bv     = (const float*)d_in[6];
    const float* wo     = (const float*)d_in[7];
    const float* bo     = (const float*)d_in[8];
    const float* w1     = (const float*)d_in[9];
    const float* b1     = (const float*)d_in[10];
    const float* w2     = (const float*)d_in[11];
    const float* b2     = (const float*)d_in[12];
    const float* alpha1 = (const float*)d_in[13];
    const float* beta1  = (const float*)d_in[14];
    const float* alpha2 = (const float*)d_in[15];
    const float* beta2  = (const float*)d_in[16];
    const int*   mask   = (const int*)d_in[17];

    float *q, *k, *v, *ctx, *tmp, *x1, *ff1;
    cudaGetSymbolAddress((void**)&q,   g_q);
    cudaGetSymbolAddress((void**)&k,   g_k);
    cudaGetSymbolAddress((void**)&v,   g_v);
    cudaGetSymbolAddress((void**)&ctx, g_ctx);
    cudaGetSymbolAddress((void**)&tmp, g_tmp);
    cudaGetSymbolAddress((void**)&x1,  g_x1);
    cudaGetSymbolAddress((void**)&ff1, g_ff1);

    static int attn_smem = (int)sizeof(AttnSmem);
    cudaFuncSetAttribute(attn_kernel, cudaFuncAttributeMaxDynamicSharedMemorySize, attn_smem);

    dim3 blk(256);
    dim3 gD(Dc / 128, Mc / 128);     // (6, 32)
    dim3 gF(DFFc / 128, Mc / 128);   // (24, 32)

    // QKV projections
    mma_gemm<0><<<gD, blk>>>(x, wq, bq, q, Dc, Dc);
    mma_gemm<0><<<gD, blk>>>(x, wk, bk, k, Dc, Dc);
    mma_gemm<0><<<gD, blk>>>(x, wv, bv, v, Dc, Dc);

    // Fused flash attention
    attn_kernel<<<dim3(Sc / 64, Bc * Hc), blk, attn_smem>>>(q, k, v, mask, ctx);

    // Output projection, residual + LN1
    mma_gemm<0><<<gD, blk>>>(ctx, wo, bo, tmp, Dc, Dc);
    add_ln_kernel<<<Mc, blk>>>(x, tmp, alpha1, beta1, x1);

    // FFN
    mma_gemm<1><<<gF, blk>>>(x1, w1, b1, ff1, DFFc, Dc);
    mma_gemm<0><<<gD, blk>>>(ff1, w2, b2, tmp, Dc, DFFc);
    add_ln_kernel<<<Mc, blk>>>(x1, tmp, alpha2, beta2, (float*)d_out);
}

// round 4
// speedup vs baseline: 2.2397x; 1.4912x over previous
#include <cuda_runtime.h>
#include <cuda_bf16.h>
#include <stdint.h>
#include <math.h>

// Problem constants
static constexpr int Bc   = 2;
static constexpr int Sc   = 2048;
static constexpr int Dc   = 768;
static constexpr int Hc   = 12;
static constexpr int DKc  = 64;
static constexpr int DFFc = 3072;
static constexpr int Mc   = Bc * Sc;   // 4096 rows

// Scratch (static device globals: allocation-free)
__device__ float g_q  [Mc * Dc];
__device__ float g_k  [Mc * Dc];
__device__ float g_v  [Mc * Dc];
__device__ float g_ctx[Mc * Dc];
__device__ float g_tmp[Mc * Dc];
__device__ float g_x1 [Mc * Dc];
__device__ float g_ff1[Mc * DFFc];

// bf16 hi/lo split copies for tensor-core attention
__device__ __nv_bfloat16 g_Qh[Mc * Dc], g_Ql[Mc * Dc];
__device__ __nv_bfloat16 g_Vh[Mc * Dc], g_Vl[Mc * Dc];
__device__ __nv_bfloat16 g_Kth[Bc * Hc * DKc * Sc], g_Ktl[Bc * Hc * DKc * Sc]; // [bh][d][s]

// ---------------------------------------------------------------------------
// helpers
// ---------------------------------------------------------------------------
__device__ __forceinline__ uint32_t sptr(const void* p) {
    return (uint32_t)__cvta_generic_to_shared(p);
}
__device__ __forceinline__ void ldsm4(uint32_t r[4], uint32_t addr) {
    asm volatile("ldmatrix.sync.aligned.m8n8.x4.shared.b16 {%0,%1,%2,%3},[%4];"
                 : "=r"(r[0]), "=r"(r[1]), "=r"(r[2]), "=r"(r[3]) : "r"(addr));
}
__device__ __forceinline__ void ldsm4t(uint32_t r[4], uint32_t addr) {
    asm volatile("ldmatrix.sync.aligned.m8n8.x4.trans.shared.b16 {%0,%1,%2,%3},[%4];"
                 : "=r"(r[0]), "=r"(r[1]), "=r"(r[2]), "=r"(r[3]) : "r"(addr));
}
__device__ __forceinline__ void mma16816(float c[4], const uint32_t a[4],
                                         uint32_t b0, uint32_t b1) {
    asm volatile(
        "mma.sync.aligned.m16n8k16.row.col.f32.bf16.bf16.f32 "
        "{%0,%1,%2,%3},{%4,%5,%6,%7},{%8,%9},{%0,%1,%2,%3};"
        : "+f"(c[0]), "+f"(c[1]), "+f"(c[2]), "+f"(c[3])
        : "r"(a[0]), "r"(a[1]), "r"(a[2]), "r"(a[3]), "r"(b0), "r"(b1));
}
__device__ __forceinline__ void cvt4(float4 f, __nv_bfloat16* hp, __nv_bfloat16* lp) {
    float v[4] = {f.x, f.y, f.z, f.w};
    __nv_bfloat16 h[4], l[4];
#pragma unroll
    for (int i = 0; i < 4; i++) {
        h[i] = __float2bfloat16(v[i]);
        l[i] = __float2bfloat16(v[i] - __bfloat162float(h[i]));
    }
    *(uint2*)hp = *(uint2*)h;
    *(uint2*)lp = *(uint2*)l;
}
__device__ __forceinline__ void split2(float a, float b, uint32_t& h, uint32_t& l) {
    __nv_bfloat16 ha = __float2bfloat16(a), hb = __float2bfloat16(b);
    float la = a - __bfloat162float(ha), lb = b - __bfloat162float(hb);
    __nv_bfloat162 H; H.x = ha; H.y = hb;
    __nv_bfloat162 L; L.x = __float2bfloat16(la); L.y = __float2bfloat16(lb);
    h = *(uint32_t*)&H;
    l = *(uint32_t*)&L;
}
__device__ __forceinline__ void cpasync16(void* smem, const void* gmem) {
    asm volatile("cp.async.cg.shared.global [%0],[%1],16;"
                 :: "r"(sptr(smem)), "l"(gmem));
}
__device__ __forceinline__ void cpcommit() { asm volatile("cp.async.commit_group;"); }
__device__ __forceinline__ void cpwait0()  { asm volatile("cp.async.wait_group 0;"); }

// ---------------------------------------------------------------------------
// Tensor-core GEMM: C[M,N] = A[M,K] @ W[K,N] + bias   (EPI==1: ReLU)
// bf16 3-split, fp32 accum. BM=BN=128, BK=32, 8 warps. (unchanged from R3)
// ---------------------------------------------------------------------------
template<int EPI>
__global__ __launch_bounds__(256, 1)
void mma_gemm(const float* __restrict__ A, const float* __restrict__ W,
              const float* __restrict__ bias, float* __restrict__ C,
              int Ndim, int Kdim)
{
    __shared__ __nv_bfloat16 Ah[128][40], Al[128][40];
    __shared__ __nv_bfloat16 Wh[32][136], Wl[32][136];

    const int tid  = threadIdx.x;
    const int lane = tid & 31;
    const int wid  = tid >> 5;
    const int wm   = (wid & 1) * 64;
    const int wn   = (wid >> 1) * 32;
    const int bM   = blockIdx.y * 128;
    const int bN   = blockIdx.x * 128;

    const int arow = tid >> 1;
    const int acol = (tid & 1) * 16;
    const int wrow = tid >> 3;
    const int wcol = (tid & 7) * 16;

    const float* Abase = A + (size_t)(bM + arow) * Kdim + acol;
    const float* Wbase = W + (size_t)wrow * Ndim + bN + wcol;
    const size_t WkStride = (size_t)32 * Ndim;

    float4 ra[4], rw[4];
    const int T = Kdim / 32;

#pragma unroll
    for (int j = 0; j < 4; j++) ra[j] = *(const float4*)(Abase + j * 4);
#pragma unroll
    for (int j = 0; j < 4; j++) rw[j] = *(const float4*)(Wbase + j * 4);

    float acc[4][4][4];
#pragma unroll
    for (int a = 0; a < 4; a++)
#pragma unroll
        for (int b = 0; b < 4; b++)
#pragma unroll
            for (int c = 0; c < 4; c++) acc[a][b][c] = 0.f;

    const int lr    = lane & 15;
    const int lc8   = (lane >> 4) * 8;
    const int brow  = (lane & 7) + ((lane >> 3) & 1) * 8;
    const int bcol8 = (lane >> 4) * 8;

    for (int t = 0; t < T; t++) {
        __syncthreads();
#pragma unroll
        for (int j = 0; j < 4; j++) cvt4(ra[j], &Ah[arow][acol + j * 4], &Al[arow][acol + j * 4]);
#pragma unroll
        for (int j = 0; j < 4; j++) cvt4(rw[j], &Wh[wrow][wcol + j * 4], &Wl[wrow][wcol + j * 4]);
        __syncthreads();

        if (t + 1 < T) {
            const float* Ap = Abase + (t + 1) * 32;
            const float* Wp = Wbase + (size_t)(t + 1) * WkStride;
#pragma unroll
            for (int j = 0; j < 4; j++) ra[j] = *(const float4*)(Ap + j * 4);
#pragma unroll
            for (int j = 0; j < 4; j++) rw[j] = *(const float4*)(Wp + j * 4);
        }

#pragma unroll
        for (int ks = 0; ks < 32; ks += 16) {
            uint32_t ah[4][4], alr[4][4];
#pragma unroll
            for (int mi = 0; mi < 4; mi++) {
                ldsm4(ah[mi],  sptr(&Ah[wm + mi * 16 + lr][ks + lc8]));
                ldsm4(alr[mi], sptr(&Al[wm + mi * 16 + lr][ks + lc8]));
            }
#pragma unroll
            for (int p = 0; p < 2; p++) {
                uint32_t bh[4], bl[4];
                ldsm4t(bh, sptr(&Wh[ks + brow][wn + p * 16 + bcol8]));
                ldsm4t(bl, sptr(&Wl[ks + brow][wn + p * 16 + bcol8]));
#pragma unroll
                for (int s = 0; s < 2; s++) {
                    const int ni = p * 2 + s;
#pragma unroll
                    for (int mi = 0; mi < 4; mi++) {
                        mma16816(acc[mi][ni], ah[mi],  bh[s * 2], bh[s * 2 + 1]);
                        mma16816(acc[mi][ni], ah[mi],  bl[s * 2], bl[s * 2 + 1]);
                        mma16816(acc[mi][ni], alr[mi], bh[s * 2], bh[s * 2 + 1]);
                    }
                }
            }
        }
    }

    const int gr = lane >> 2, gc = (lane & 3) * 2;
#pragma unroll
    for (int mi = 0; mi < 4; mi++) {
#pragma unroll
        for (int ni = 0; ni < 4; ni++) {
            int row = bM + wm + mi * 16 + gr;
            int col = bN + wn + ni * 8 + gc;
            float b0 = bias[col], b1 = bias[col + 1];
            float v0 = acc[mi][ni][0] + b0, v1 = acc[mi][ni][1] + b1;
            float v2 = acc[mi][ni][2] + b0, v3 = acc[mi][ni][3] + b1;
            if (EPI) {
                v0 = fmaxf(v0, 0.f); v1 = fmaxf(v1, 0.f);
                v2 = fmaxf(v2, 0.f); v3 = fmaxf(v3, 0.f);
            }
            *(float2*)&C[(size_t)row * Ndim + col]       = make_float2(v0, v1);
            *(float2*)&C[(size_t)(row + 8) * Ndim + col] = make_float2(v2, v3);
        }
    }
}

// ---------------------------------------------------------------------------
// qkv split/convert: q,k,v fp32 -> bf16 hi/lo; K additionally transposed
// to [bh][d][s] for direct ldmatrix B-fragment feeding.
// ---------------------------------------------------------------------------
__global__ __launch_bounds__(256)
void qkv_cvt(const float* __restrict__ q, const float* __restrict__ k,
             const float* __restrict__ v)
{
    size_t i4 = ((size_t)blockIdx.x * 256 + threadIdx.x) * 4;
    int row = (int)(i4 / Dc);
    int col = (int)(i4 - (size_t)row * Dc);

    float4 qv = *(const float4*)(q + i4);
    float4 kv = *(const float4*)(k + i4);
    float4 vv = *(const float4*)(v + i4);

    cvt4(qv, &g_Qh[i4], &g_Ql[i4]);
    cvt4(vv, &g_Vh[i4], &g_Vl[i4]);

    int b = row >> 11, s = row & (Sc - 1);
    int h = col >> 6,  d = col & (DKc - 1);
    size_t base = ((size_t)(b * Hc + h) * DKc + d) * Sc + s;
    float kf[4] = {kv.x, kv.y, kv.z, kv.w};
#pragma unroll
    for (int t = 0; t < 4; t++) {
        __nv_bfloat16 hh = __float2bfloat16(kf[t]);
        g_Kth[base + (size_t)t * Sc] = hh;
        g_Ktl[base + (size_t)t * Sc] = __float2bfloat16(kf[t] - __bfloat162float(hh));
    }
}

// ---------------------------------------------------------------------------
// Tensor-core flash attention. QT=128 (8 warps x 16 rows), KT=64.
// 3-term bf16 split for QK^T and PV. Softmax fully in registers.
// ---------------------------------------------------------------------------
struct AttnSmem2 {
    __nv_bfloat16 Qh[128][72];
    __nv_bfloat16 Ql[128][72];
    __nv_bfloat16 Kh[64][72];   // [d][kseq]
    __nv_bfloat16 Kl[64][72];
    __nv_bfloat16 Vh[64][72];   // [kseq][d]
    __nv_bfloat16 Vl[64][72];
};

__global__ __launch_bounds__(256, 2)
void attn_mma(const int* __restrict__ mask, float* __restrict__ ctx)
{
    extern __shared__ char sraw[];
    AttnSmem2& sm = *reinterpret_cast<AttnSmem2*>(sraw);

    const int tid = threadIdx.x, lane = tid & 31, wid = tid >> 5;
    const int qb = blockIdx.x, bh = blockIdx.y;
    const int b = bh / Hc, h = bh - b * Hc;
    const int q0 = qb * 128, rb = b * Sc, c0 = h * DKc;

    // --- stage Q tile and build register fragments ---
    {
        int r = tid >> 1, cb = (tid & 1) * 32;
        const __nv_bfloat16* gqh = g_Qh + (size_t)(rb + q0 + r) * Dc + c0 + cb;
        const __nv_bfloat16* gql = g_Ql + (size_t)(rb + q0 + r) * Dc + c0 + cb;
#pragma unroll
        for (int j = 0; j < 4; j++) {
            cpasync16(&sm.Qh[r][cb + j * 8], gqh + j * 8);
            cpasync16(&sm.Ql[r][cb + j * 8], gql + j * 8);
        }
        cpcommit(); cpwait0();
    }
    __syncthreads();

    const int lr = lane & 15, lc8 = (lane >> 4) * 8;
    const int wq0 = wid * 16;
    uint32_t qh[4][4], ql[4][4];
#pragma unroll
    for (int kt = 0; kt < 4; kt++) {
        ldsm4(qh[kt], sptr(&sm.Qh[wq0 + lr][kt * 16 + lc8]));
        ldsm4(ql[kt], sptr(&sm.Ql[wq0 + lr][kt * 16 + lc8]));
    }

    const int g  = lane >> 2, tg = lane & 3;
    const int brow  = (lane & 7) + ((lane >> 3) & 1) * 8;
    const int bcol8 = (lane >> 4) * 8;

    float oacc[8][4];
#pragma unroll
    for (int i = 0; i < 8; i++)
#pragma unroll
        for (int j = 0; j < 4; j++) oacc[i][j] = 0.f;
    float m0 = -INFINITY, m1 = -INFINITY, l0 = 0.f, l1 = 0.f;

    // K/V staging roles
    const int kr = tid >> 2, kcb = (tid & 3) * 16;
    const __nv_bfloat16* gKh = g_Kth + ((size_t)bh * DKc + kr) * Sc;
    const __nv_bfloat16* gKl = g_Ktl + ((size_t)bh * DKc + kr) * Sc;

    const int* mr0base = mask + (size_t)(q0 + wq0 + g) * Sc + 2 * tg;

    for (int k0 = 0; k0 < Sc; k0 += 64) {
        // stage K (transposed) and V
        cpasync16(&sm.Kh[kr][kcb],     gKh + k0 + kcb);
        cpasync16(&sm.Kh[kr][kcb + 8], gKh + k0 + kcb + 8);
        cpasync16(&sm.Kl[kr][kcb],     gKl + k0 + kcb);
        cpasync16(&sm.Kl[kr][kcb + 8], gKl + k0 + kcb + 8);
        {
            const __nv_bfloat16* gvh = g_Vh + (size_t)(rb + k0 + kr) * Dc + c0 + kcb;
            const __nv_bfloat16* gvl = g_Vl + (size_t)(rb + k0 + kr) * Dc + c0 + kcb;
            cpasync16(&sm.Vh[kr][kcb],     gvh);
            cpasync16(&sm.Vh[kr][kcb + 8], gvh + 8);
            cpasync16(&sm.Vl[kr][kcb],     gvl);
            cpasync16(&sm.Vl[kr][kcb + 8], gvl + 8);
        }
        cpcommit(); cpwait0();
        __syncthreads();

        // ---- S = Q K^T (3-term split) ----
        float s[8][4];
#pragma unroll
        for (int i = 0; i < 8; i++)
#pragma unroll
            for (int j = 0; j < 4; j++) s[i][j] = 0.f;

#pragma unroll
        for (int kt = 0; kt < 4; kt++) {
#pragma unroll
            for (int p = 0; p < 4; p++) {
                uint32_t kbh[4], kbl[4];
                ldsm4t(kbh, sptr(&sm.Kh[kt * 16 + brow][p * 16 + bcol8]));
                ldsm4t(kbl, sptr(&sm.Kl[kt * 16 + brow][p * 16 + bcol8]));
                mma16816(s[2 * p],     qh[kt], kbh[0], kbh[1]);
                mma16816(s[2 * p],     qh[kt], kbl[0], kbl[1]);
                mma16816(s[2 * p],     ql[kt], kbh[0], kbh[1]);
                mma16816(s[2 * p + 1], qh[kt], kbh[2], kbh[3]);
                mma16816(s[2 * p + 1], qh[kt], kbl[2], kbl[3]);
                mma16816(s[2 * p + 1], ql[kt], kbh[2], kbh[3]);
            }
        }

        // ---- scale + mask ----
        const int* mr0 = mr0base + k0;
        const int* mr1 = mr0 + 8 * Sc;
#pragma unroll
        for (int ni = 0; ni < 8; ni++) {
            int2 ma = *(const int2*)(mr0 + 8 * ni);
            int2 mb = *(const int2*)(mr1 + 8 * ni);
            s[ni][0] = ma.x ? s[ni][0] * 0.125f : -1e9f;
            s[ni][1] = ma.y ? s[ni][1] * 0.125f : -1e9f;
            s[ni][2] = mb.x ? s[ni][2] * 0.125f : -1e9f;
            s[ni][3] = mb.y ? s[ni][3] * 0.125f : -1e9f;
        }

        // ---- online softmax (row stats via 4-lane shfl groups) ----
        float mx0 = -INFINITY, mx1 = -INFINITY;
#pragma unroll
        for (int ni = 0; ni < 8; ni++) {
            mx0 = fmaxf(mx0, fmaxf(s[ni][0], s[ni][1]));
            mx1 = fmaxf(mx1, fmaxf(s[ni][2], s[ni][3]));
        }
        mx0 = fmaxf(mx0, __shfl_xor_sync(0xffffffffu, mx0, 1));
        mx0 = fmaxf(mx0, __shfl_xor_sync(0xffffffffu, mx0, 2));
        mx1 = fmaxf(mx1, __shfl_xor_sync(0xffffffffu, mx1, 1));
        mx1 = fmaxf(mx1, __shfl_xor_sync(0xffffffffu, mx1, 2));

        float mn0 = fmaxf(m0, mx0), mn1 = fmaxf(m1, mx1);
        float a0 = __expf(m0 - mn0), a1 = __expf(m1 - mn1);
        m0 = mn0; m1 = mn1;

        float sum0 = 0.f, sum1 = 0.f;
#pragma unroll
        for (int ni = 0; ni < 8; ni++) {
            s[ni][0] = __expf(s[ni][0] - mn0); sum0 += s[ni][0];
            s[ni][1] = __expf(s[ni][1] - mn0); sum0 += s[ni][1];
            s[ni][2] = __expf(s[ni][2] - mn1); sum1 += s[ni][2];
            s[ni][3] = __expf(s[ni][3] - mn1); sum1 += s[ni][3];
        }
        sum0 += __shfl_xor_sync(0xffffffffu, sum0, 1);
        sum0 += __shfl_xor_sync(0xffffffffu, sum0, 2);
        sum1 += __shfl_xor_sync(0xffffffffu, sum1, 1);
        sum1 += __shfl_xor_sync(0xffffffffu, sum1, 2);
        l0 = l0 * a0 + sum0;
        l1 = l1 * a1 + sum1;

#pragma unroll
        for (int ni = 0; ni < 8; ni++) {
            oacc[ni][0] *= a0; oacc[ni][1] *= a0;
            oacc[ni][2] *= a1; oacc[ni][3] *= a1;
        }

        // ---- O += P @ V (3-term split), P packed from S fragments ----
#pragma unroll
        for (int kt = 0; kt < 4; kt++) {
            uint32_t pah[4], pal[4];
            split2(s[2 * kt][0],     s[2 * kt][1],     pah[0], pal[0]);
            split2(s[2 * kt][2],     s[2 * kt][3],     pah[1], pal[1]);
            split2(s[2 * kt + 1][0], s[2 * kt + 1][1], pah[2], pal[2]);
            split2(s[2 * kt + 1][2], s[2 * kt + 1][3], pah[3], pal[3]);
#pragma unroll
            for (int p = 0; p < 4; p++) {
                uint32_t vbh[4], vbl[4];
                ldsm4t(vbh, sptr(&sm.Vh[kt * 16 + brow][p * 16 + bcol8]));
                ldsm4t(vbl, sptr(&sm.Vl[kt * 16 + brow][p * 16 + bcol8]));
                mma16816(oacc[2 * p],     pah, vbh[0], vbh[1]);
                mma16816(oacc[2 * p],     pah, vbl[0], vbl[1]);
                mma16816(oacc[2 * p],     pal, vbh[0], vbh[1]);
                mma16816(oacc[2 * p + 1], pah, vbh[2], vbh[3]);
                mma16816(oacc[2 * p + 1], pah, vbl[2], vbl[3]);
                mma16816(oacc[2 * p + 1], pal, vbh[2], vbh[3]);
            }
        }
        __syncthreads();
    }

    // ---- epilogue ----
    float i0 = 1.f / l0, i1 = 1.f / l1;
    const int r0 = rb + q0 + wq0 + g;
#pragma unroll
    for (int ni = 0; ni < 8; ni++) {
        int col = c0 + 8 * ni + 2 * tg;
        *(float2*)&ctx[(size_t)r0 * Dc + col] =
            make_float2(oacc[ni][0] * i0, oacc[ni][1] * i0);
        *(float2*)&ctx[(size_t)(r0 + 8) * Dc + col] =
            make_float2(oacc[ni][2] * i1, oacc[ni][3] * i1);
    }
}

// ---------------------------------------------------------------------------
// out = alpha * ((x+y) - mean) / (std_unbiased + eps) + beta, row of 768
// ---------------------------------------------------------------------------
__global__ __launch_bounds__(256)
void add_ln_kernel(const float* __restrict__ x, const float* __restrict__ y,
                   const float* __restrict__ alpha, const float* __restrict__ beta,
                   float* __restrict__ out)
{
    const int row = blockIdx.x;
    const int tid = threadIdx.x;
    const float* xr = x + (size_t)row * Dc;
    const float* yr = y + (size_t)row * Dc;

    __shared__ float red[8];
    __shared__ float sm_mean, sm_scale;

    float v[3];
    float s = 0.f;
#pragma unroll
    for (int t = 0; t < 3; t++) {
        v[t] = xr[tid + 256 * t] + yr[tid + 256 * t];
        s += v[t];
    }
#pragma unroll
    for (int o = 16; o > 0; o >>= 1) s += __shfl_xor_sync(0xFFFFFFFFu, s, o);
    if ((tid & 31) == 0) red[tid >> 5] = s;
    __syncthreads();
    if (tid == 0) {
        float tot = 0.f;
#pragma unroll
        for (int w = 0; w < 8; w++) tot += red[w];
        sm_mean = tot * (1.0f / (float)Dc);
    }
    __syncthreads();
    const float mean = sm_mean;

    float sq = 0.f;
#pragma unroll
    for (int t = 0; t < 3; t++) {
        float d = v[t] - mean;
        sq += d * d;
    }
#pragma unroll
    for (int o = 16; o > 0; o >>= 1) sq += __shfl_xor_sync(0xFFFFFFFFu, sq, o);
    if ((tid & 31) == 0) red[tid >> 5] = sq;
    __syncthreads();
    if (tid == 0) {
        float tot = 0.f;
#pragma unroll
        for (int w = 0; w < 8; w++) tot += red[w];
        float var = tot * (1.0f / (float)(Dc - 1));
        sm_scale = 1.0f / (sqrtf(var) + 1e-6f);
    }
    __syncthreads();

    const float sc = sm_scale * alpha[0];
    const float bt = beta[0];
#pragma unroll
    for (int t = 0; t < 3; t++)
        out[(size_t)row * Dc + tid + 256 * t] = (v[t] - mean) * sc + bt;
}

// ---------------------------------------------------------------------------
extern "C" void kernel_launch(void* const* d_in, const int* in_sizes, int n_in,
                              void* d_out, int out_size)
{
    const float* x      = (const float*)d_in[0];
    const float* wq     = (const float*)d_in[1];
    const float* bq     = (const float*)d_in[2];
    const float* wk     = (const float*)d_in[3];
    const float* bk     = (const float*)d_in[4];
    const float* wv     = (const float*)d_in[5];
    const float* bv     = (const float*)d_in[6];
    const float* wo     = (const float*)d_in[7];
    const float* bo     = (const float*)d_in[8];
    const float* w1     = (const float*)d_in[9];
    const float* b1     = (const float*)d_in[10];
    const float* w2     = (const float*)d_in[11];
    const float* b2     = (const float*)d_in[12];
    const float* alpha1 = (const float*)d_in[13];
    const float* beta1  = (const float*)d_in[14];
    const float* alpha2 = (const float*)d_in[15];
    const float* beta2  = (const float*)d_in[16];
    const int*   mask   = (const int*)d_in[17];

    float *q, *k, *v, *ctx, *tmp, *x1, *ff1;
    cudaGetSymbolAddress((void**)&q,   g_q);
    cudaGetSymbolAddress((void**)&k,   g_k);
    cudaGetSymbolAddress((void**)&v,   g_v);
    cudaGetSymbolAddress((void**)&ctx, g_ctx);
    cudaGetSymbolAddress((void**)&tmp, g_tmp);
    cudaGetSymbolAddress((void**)&x1,  g_x1);
    cudaGetSymbolAddress((void**)&ff1, g_ff1);

    static int attn_smem = (int)sizeof(AttnSmem2);
    static bool attr_set = false;
    if (!attr_set) {
        cudaFuncSetAttribute(attn_mma, cudaFuncAttributeMaxDynamicSharedMemorySize, attn_smem);
        attr_set = true;
    }

    dim3 blk(256);
    dim3 gD(Dc / 128, Mc / 128);     // (6, 32)
    dim3 gF(DFFc / 128, Mc / 128);   // (24, 32)

    // QKV projections
    mma_gemm<0><<<gD, blk>>>(x, wq, bq, q, Dc, Dc);
    mma_gemm<0><<<gD, blk>>>(x, wk, bk, k, Dc, Dc);
    mma_gemm<0><<<gD, blk>>>(x, wv, bv, v, Dc, Dc);

    // split q,k,v to bf16 hi/lo (+ K transpose per head)
    qkv_cvt<<<(Mc * Dc / 4 + 255) / 256, blk>>>(q, k, v);

    // tensor-core flash attention
    attn_mma<<<dim3(Sc / 128, Bc * Hc), blk, attn_smem>>>(mask, ctx);

    // Output projection, residual + LN1
    mma_gemm<0><<<gD, blk>>>(ctx, wo, bo, tmp, Dc, Dc);
    add_ln_kernel<<<Mc, blk>>>(x, tmp, alpha1, beta1, x1);

    // FFN
    mma_gemm<1><<<gF, blk>>>(x1, w1, b1, ff1, DFFc, Dc);
    mma_gemm<0><<<gD, blk>>>(ff1, w2, b2, tmp, Dc, DFFc);
    add_ln_kernel<<<Mc, blk>>>(x1, tmp, alpha2, beta2, (float*)d_out);
}

// round 6
// speedup vs baseline: 2.6557x; 1.1857x over previous
#include <cuda_runtime.h>
#include <cuda_bf16.h>
#include <cuda_fp16.h>
#include <stdint.h>
#include <math.h>

// Problem constants
static constexpr int Bc   = 2;
static constexpr int Sc   = 2048;
static constexpr int Dc   = 768;
static constexpr int Hc   = 12;
static constexpr int DKc  = 64;
static constexpr int DFFc = 3072;
static constexpr int Mc   = Bc * Sc;   // 4096 rows

// f32 scratch
__device__ float g_k  [Mc * Dc];
__device__ float g_ctx[Mc * Dc];
__device__ float g_tmp[Mc * Dc];
__device__ float g_x1 [Mc * Dc];
__device__ float g_ff1[Mc * DFFc];

// attention operands (bf16 hi/lo)
__device__ __nv_bfloat16 g_Qh[Mc * Dc], g_Ql[Mc * Dc];
__device__ __nv_bfloat16 g_Vh[Mc * Dc], g_Vl[Mc * Dc];
__device__ __nv_bfloat16 g_Kth[Bc * Hc * DKc * Sc], g_Ktl[Bc * Hc * DKc * Sc]; // [bh][d][s]

// ---------------------------------------------------------------------------
// helpers
// ---------------------------------------------------------------------------
__device__ __forceinline__ uint32_t sptr(const void* p) {
    return (uint32_t)__cvta_generic_to_shared(p);
}
__device__ __forceinline__ void ldsm4(uint32_t r[4], uint32_t addr) {
    asm volatile("ldmatrix.sync.aligned.m8n8.x4.shared.b16 {%0,%1,%2,%3},[%4];"
                 : "=r"(r[0]), "=r"(r[1]), "=r"(r[2]), "=r"(r[3]) : "r"(addr));
}
__device__ __forceinline__ void ldsm4t(uint32_t r[4], uint32_t addr) {
    asm volatile("ldmatrix.sync.aligned.m8n8.x4.trans.shared.b16 {%0,%1,%2,%3},[%4];"
                 : "=r"(r[0]), "=r"(r[1]), "=r"(r[2]), "=r"(r[3]) : "r"(addr));
}
// bf16 mma
__device__ __forceinline__ void mma16816(float c[4], const uint32_t a[4],
                                         uint32_t b0, uint32_t b1) {
    asm volatile(
        "mma.sync.aligned.m16n8k16.row.col.f32.bf16.bf16.f32 "
        "{%0,%1,%2,%3},{%4,%5,%6,%7},{%8,%9},{%0,%1,%2,%3};"
        : "+f"(c[0]), "+f"(c[1]), "+f"(c[2]), "+f"(c[3])
        : "r"(a[0]), "r"(a[1]), "r"(a[2]), "r"(a[3]), "r"(b0), "r"(b1));
}
// fp16 mma (f32 accum)
__device__ __forceinline__ void mma16816h(float c[4], const uint32_t a[4],
                                          uint32_t b0, uint32_t b1) {
    asm volatile(
        "mma.sync.aligned.m16n8k16.row.col.f32.f16.f16.f32 "
        "{%0,%1,%2,%3},{%4,%5,%6,%7},{%8,%9},{%0,%1,%2,%3};"
        : "+f"(c[0]), "+f"(c[1]), "+f"(c[2]), "+f"(c[3])
        : "r"(a[0]), "r"(a[1]), "r"(a[2]), "r"(a[3]), "r"(b0), "r"(b1));
}
__device__ __forceinline__ void cvt4(float4 f, __nv_bfloat16* hp, __nv_bfloat16* lp) {
    float v[4] = {f.x, f.y, f.z, f.w};
    __nv_bfloat16 h[4], l[4];
#pragma unroll
    for (int i = 0; i < 4; i++) {
        h[i] = __float2bfloat16(v[i]);
        l[i] = __float2bfloat16(v[i] - __bfloat162float(h[i]));
    }
    *(uint2*)hp = *(uint2*)h;
    *(uint2*)lp = *(uint2*)l;
}
__device__ __forceinline__ void cvt4h(float4 f, __half* hp, __half* lp) {
    float v[4] = {f.x, f.y, f.z, f.w};
    __half h[4], l[4];
#pragma unroll
    for (int i = 0; i < 4; i++) {
        h[i] = __float2half_rn(v[i]);
        l[i] = __float2half_rn(v[i] - __half2float(h[i]));
    }
    *(uint2*)hp = *(uint2*)h;
    *(uint2*)lp = *(uint2*)l;
}
__device__ __forceinline__ void round4h(float4 f, __half* hp) {
    __half h[4] = {__float2half_rn(f.x), __float2half_rn(f.y),
                   __float2half_rn(f.z), __float2half_rn(f.w)};
    *(uint2*)hp = *(uint2*)h;
}
__device__ __forceinline__ void split2(float a, float b, uint32_t& h, uint32_t& l) {
    __nv_bfloat16 ha = __float2bfloat16(a), hb = __float2bfloat16(b);
    float la = a - __bfloat162float(ha), lb = b - __bfloat162float(hb);
    __nv_bfloat162 H; H.x = ha; H.y = hb;
    __nv_bfloat162 L; L.x = __float2bfloat16(la); L.y = __float2bfloat16(lb);
    h = *(uint32_t*)&H;
    l = *(uint32_t*)&L;
}
__device__ __forceinline__ void cpasync16(void* smem, const void* gmem) {
    asm volatile("cp.async.cg.shared.global [%0],[%1],16;"
                 :: "r"(sptr(smem)), "l"(gmem));
}
__device__ __forceinline__ void cpcommit() { asm volatile("cp.async.commit_group;"); }
__device__ __forceinline__ void cpwait0()  { asm volatile("cp.async.wait_group 0;"); }

// ---------------------------------------------------------------------------
// 3-term bf16 GEMM (AhWh + AhWl + AlWh). Used for Q/K projections.
// EMIT_HL=1: write bf16 hi/lo split instead of f32.
// ---------------------------------------------------------------------------
template<int EMIT_HL>
__global__ __launch_bounds__(256, 1)
void mma_gemm3(const float* __restrict__ A, const float* __restrict__ W,
               const float* __restrict__ bias, float* __restrict__ Cf,
               __nv_bfloat16* __restrict__ Ch, __nv_bfloat16* __restrict__ Cl,
               int Ndim, int Kdim)
{
    __shared__ __nv_bfloat16 Ah[128][40], Al[128][40];
    __shared__ __nv_bfloat16 Wh[32][136], Wl[32][136];

    const int tid  = threadIdx.x;
    const int lane = tid & 31;
    const int wid  = tid >> 5;
    const int wm   = (wid & 1) * 64;
    const int wn   = (wid >> 1) * 32;
    const int bM   = blockIdx.y * 128;
    const int bN   = blockIdx.x * 128;

    const int arow = tid >> 1;
    const int acol = (tid & 1) * 16;
    const int wrow = tid >> 3;
    const int wcol = (tid & 7) * 16;

    const float* Abase = A + (size_t)(bM + arow) * Kdim + acol;
    const float* Wbase = W + (size_t)wrow * Ndim + bN + wcol;
    const size_t WkStride = (size_t)32 * Ndim;

    float4 ra[4], rw[4];
    const int T = Kdim / 32;

#pragma unroll
    for (int j = 0; j < 4; j++) ra[j] = *(const float4*)(Abase + j * 4);
#pragma unroll
    for (int j = 0; j < 4; j++) rw[j] = *(const float4*)(Wbase + j * 4);

    float acc[4][4][4];
#pragma unroll
    for (int a = 0; a < 4; a++)
#pragma unroll
        for (int b = 0; b < 4; b++)
#pragma unroll
            for (int c = 0; c < 4; c++) acc[a][b][c] = 0.f;

    const int lr    = lane & 15;
    const int lc8   = (lane >> 4) * 8;
    const int brow  = (lane & 7) + ((lane >> 3) & 1) * 8;
    const int bcol8 = (lane >> 4) * 8;

    for (int t = 0; t < T; t++) {
        __syncthreads();
#pragma unroll
        for (int j = 0; j < 4; j++) cvt4(ra[j], &Ah[arow][acol + j * 4], &Al[arow][acol + j * 4]);
#pragma unroll
        for (int j = 0; j < 4; j++) cvt4(rw[j], &Wh[wrow][wcol + j * 4], &Wl[wrow][wcol + j * 4]);
        __syncthreads();

        if (t + 1 < T) {
            const float* Ap = Abase + (t + 1) * 32;
            const float* Wp = Wbase + (size_t)(t + 1) * WkStride;
#pragma unroll
            for (int j = 0; j < 4; j++) ra[j] = *(const float4*)(Ap + j * 4);
#pragma unroll
            for (int j = 0; j < 4; j++) rw[j] = *(const float4*)(Wp + j * 4);
        }

#pragma unroll
        for (int ks = 0; ks < 32; ks += 16) {
            uint32_t ah[4][4], alr[4][4];
#pragma unroll
            for (int mi = 0; mi < 4; mi++) {
                ldsm4(ah[mi],  sptr(&Ah[wm + mi * 16 + lr][ks + lc8]));
                ldsm4(alr[mi], sptr(&Al[wm + mi * 16 + lr][ks + lc8]));
            }
#pragma unroll
            for (int p = 0; p < 2; p++) {
                uint32_t bh[4], bl[4];
                ldsm4t(bh, sptr(&Wh[ks + brow][wn + p * 16 + bcol8]));
                ldsm4t(bl, sptr(&Wl[ks + brow][wn + p * 16 + bcol8]));
#pragma unroll
                for (int s = 0; s < 2; s++) {
                    const int ni = p * 2 + s;
#pragma unroll
                    for (int mi = 0; mi < 4; mi++) {
                        mma16816(acc[mi][ni], ah[mi],  bh[s * 2], bh[s * 2 + 1]);
                        mma16816(acc[mi][ni], ah[mi],  bl[s * 2], bl[s * 2 + 1]);
                        mma16816(acc[mi][ni], alr[mi], bh[s * 2], bh[s * 2 + 1]);
                    }
                }
            }
        }
    }

    const int gr = lane >> 2, gc = (lane & 3) * 2;
#pragma unroll
    for (int mi = 0; mi < 4; mi++) {
#pragma unroll
        for (int ni = 0; ni < 4; ni++) {
            int row = bM + wm + mi * 16 + gr;
            int col = bN + wn + ni * 8 + gc;
            float b0 = bias[col], b1 = bias[col + 1];
            float v0 = acc[mi][ni][0] + b0, v1 = acc[mi][ni][1] + b1;
            float v2 = acc[mi][ni][2] + b0, v3 = acc[mi][ni][3] + b1;
            if (EMIT_HL) {
                uint32_t h0, l0, h1, l1;
                split2(v0, v1, h0, l0);
                split2(v2, v3, h1, l1);
                *(uint32_t*)&Ch[(size_t)row * Ndim + col]       = h0;
                *(uint32_t*)&Cl[(size_t)row * Ndim + col]       = l0;
                *(uint32_t*)&Ch[(size_t)(row + 8) * Ndim + col] = h1;
                *(uint32_t*)&Cl[(size_t)(row + 8) * Ndim + col] = l1;
            } else {
                *(float2*)&Cf[(size_t)row * Ndim + col]       = make_float2(v0, v1);
                *(float2*)&Cf[(size_t)(row + 8) * Ndim + col] = make_float2(v2, v3);
            }
        }
    }
}

// ---------------------------------------------------------------------------
// 2-term fp16 GEMM: C = (Ah+Al) @ Wh, W rounded to fp16 (err ~2^-12 rel).
// Used for V, O-proj, FFN1 (+ReLU), FFN2.
// ---------------------------------------------------------------------------
template<int RELU, int EMIT_HL>
__global__ __launch_bounds__(256, 1)
void mma_gemm2(const float* __restrict__ A, const float* __restrict__ W,
               const float* __restrict__ bias, float* __restrict__ Cf,
               __nv_bfloat16* __restrict__ Ch, __nv_bfloat16* __restrict__ Cl,
               int Ndim, int Kdim)
{
    __shared__ __half Ah[128][40], Al[128][40];
    __shared__ __half Wh[32][136];

    const int tid  = threadIdx.x;
    const int lane = tid & 31;
    const int wid  = tid >> 5;
    const int wm   = (wid & 1) * 64;
    const int wn   = (wid >> 1) * 32;
    const int bM   = blockIdx.y * 128;
    const int bN   = blockIdx.x * 128;

    const int arow = tid >> 1;
    const int acol = (tid & 1) * 16;
    const int wrow = tid >> 3;
    const int wcol = (tid & 7) * 16;

    const float* Abase = A + (size_t)(bM + arow) * Kdim + acol;
    const float* Wbase = W + (size_t)wrow * Ndim + bN + wcol;
    const size_t WkStride = (size_t)32 * Ndim;

    float4 ra[4], rw[4];
    const int T = Kdim / 32;

#pragma unroll
    for (int j = 0; j < 4; j++) ra[j] = *(const float4*)(Abase + j * 4);
#pragma unroll
    for (int j = 0; j < 4; j++) rw[j] = *(const float4*)(Wbase + j * 4);

    float acc[4][4][4];
#pragma unroll
    for (int a = 0; a < 4; a++)
#pragma unroll
        for (int b = 0; b < 4; b++)
#pragma unroll
            for (int c = 0; c < 4; c++) acc[a][b][c] = 0.f;

    const int lr    = lane & 15;
    const int lc8   = (lane >> 4) * 8;
    const int brow  = (lane & 7) + ((lane >> 3) & 1) * 8;
    const int bcol8 = (lane >> 4) * 8;

    for (int t = 0; t < T; t++) {
        __syncthreads();
#pragma unroll
        for (int j = 0; j < 4; j++) cvt4h(ra[j], &Ah[arow][acol + j * 4], &Al[arow][acol + j * 4]);
#pragma unroll
        for (int j = 0; j < 4; j++) round4h(rw[j], &Wh[wrow][wcol + j * 4]);
        __syncthreads();

        if (t + 1 < T) {
            const float* Ap = Abase + (t + 1) * 32;
            const float* Wp = Wbase + (size_t)(t + 1) * WkStride;
#pragma unroll
            for (int j = 0; j < 4; j++) ra[j] = *(const float4*)(Ap + j * 4);
#pragma unroll
            for (int j = 0; j < 4; j++) rw[j] = *(const float4*)(Wp + j * 4);
        }

#pragma unroll
        for (int ks = 0; ks < 32; ks += 16) {
            uint32_t ah[4][4], alr[4][4];
#pragma unroll
            for (int mi = 0; mi < 4; mi++) {
                ldsm4(ah[mi],  sptr(&Ah[wm + mi * 16 + lr][ks + lc8]));
                ldsm4(alr[mi], sptr(&Al[wm + mi * 16 + lr][ks + lc8]));
            }
#pragma unroll
            for (int p = 0; p < 2; p++) {
                uint32_t bh[4];
                ldsm4t(bh, sptr(&Wh[ks + brow][wn + p * 16 + bcol8]));
#pragma unroll
                for (int s = 0; s < 2; s++) {
                    const int ni = p * 2 + s;
#pragma unroll
                    for (int mi = 0; mi < 4; mi++) {
                        mma16816h(acc[mi][ni], ah[mi],  bh[s * 2], bh[s * 2 + 1]);
                        mma16816h(acc[mi][ni], alr[mi], bh[s * 2], bh[s * 2 + 1]);
                    }
                }
            }
        }
    }

    const int gr = lane >> 2, gc = (lane & 3) * 2;
#pragma unroll
    for (int mi = 0; mi < 4; mi++) {
#pragma unroll
        for (int ni = 0; ni < 4; ni++) {
            int row = bM + wm + mi * 16 + gr;
            int col = bN + wn + ni * 8 + gc;
            float b0 = bias[col], b1 = bias[col + 1];
            float v0 = acc[mi][ni][0] + b0, v1 = acc[mi][ni][1] + b1;
            float v2 = acc[mi][ni][2] + b0, v3 = acc[mi][ni][3] + b1;
            if (RELU) {
                v0 = fmaxf(v0, 0.f); v1 = fmaxf(v1, 0.f);
                v2 = fmaxf(v2, 0.f); v3 = fmaxf(v3, 0.f);
            }
            if (EMIT_HL) {
                uint32_t h0, l0, h1, l1;
                split2(v0, v1, h0, l0);
                split2(v2, v3, h1, l1);
                *(uint32_t*)&Ch[(size_t)row * Ndim + col]       = h0;
                *(uint32_t*)&Cl[(size_t)row * Ndim + col]       = l0;
                *(uint32_t*)&Ch[(size_t)(row + 8) * Ndim + col] = h1;
                *(uint32_t*)&Cl[(size_t)(row + 8) * Ndim + col] = l1;
            } else {
                *(float2*)&Cf[(size_t)row * Ndim + col]       = make_float2(v0, v1);
                *(float2*)&Cf[(size_t)(row + 8) * Ndim + col] = make_float2(v2, v3);
            }
        }
    }
}

// ---------------------------------------------------------------------------
// K transpose + split: k f32 [B*S, D] -> Kth/Ktl bf16 [bh][d][s]
// ---------------------------------------------------------------------------
__global__ __launch_bounds__(256)
void k_cvt(const float* __restrict__ k)
{
    size_t i4 = ((size_t)blockIdx.x * 256 + threadIdx.x) * 4;
    int row = (int)(i4 / Dc);
    int col = (int)(i4 - (size_t)row * Dc);

    float4 kv = *(const float4*)(k + i4);

    int b = row >> 11, s = row & (Sc - 1);
    int h = col >> 6,  d = col & (DKc - 1);
    size_t base = ((size_t)(b * Hc + h) * DKc + d) * Sc + s;
    float kf[4] = {kv.x, kv.y, kv.z, kv.w};
#pragma unroll
    for (int t = 0; t < 4; t++) {
        __nv_bfloat16 hh = __float2bfloat16(kf[t]);
        g_Kth[base + (size_t)t * Sc] = hh;
        g_Ktl[base + (size_t)t * Sc] = __float2bfloat16(kf[t] - __bfloat162float(hh));
    }
}

// ---------------------------------------------------------------------------
// Tensor-core flash attention (R4, unchanged). QT=128, KT=64, 3-term bf16.
// ---------------------------------------------------------------------------
struct AttnSmem2 {
    __nv_bfloat16 Qh[128][72];
    __nv_bfloat16 Ql[128][72];
    __nv_bfloat16 Kh[64][72];
    __nv_bfloat16 Kl[64][72];
    __nv_bfloat16 Vh[64][72];
    __nv_bfloat16 Vl[64][72];
};

__global__ __launch_bounds__(256, 2)
void attn_mma(const int* __restrict__ mask, float* __restrict__ ctx)
{
    extern __shared__ char sraw[];
    AttnSmem2& sm = *reinterpret_cast<AttnSmem2*>(sraw);

    const int tid = threadIdx.x, lane = tid & 31, wid = tid >> 5;
    const int qb = blockIdx.x, bh = blockIdx.y;
    const int b = bh / Hc, h = bh - b * Hc;
    const int q0 = qb * 128, rb = b * Sc, c0 = h * DKc;

    {
        int r = tid >> 1, cb = (tid & 1) * 32;
        const __nv_bfloat16* gqh = g_Qh + (size_t)(rb + q0 + r) * Dc + c0 + cb;
        const __nv_bfloat16* gql = g_Ql + (size_t)(rb + q0 + r) * Dc + c0 + cb;
#pragma unroll
        for (int j = 0; j < 4; j++) {
            cpasync16(&sm.Qh[r][cb + j * 8], gqh + j * 8);
            cpasync16(&sm.Ql[r][cb + j * 8], gql + j * 8);
        }
        cpcommit(); cpwait0();
    }
    __syncthreads();

    const int lr = lane & 15, lc8 = (lane >> 4) * 8;
    const int wq0 = wid * 16;
    uint32_t qh[4][4], ql[4][4];
#pragma unroll
    for (int kt = 0; kt < 4; kt++) {
        ldsm4(qh[kt], sptr(&sm.Qh[wq0 + lr][kt * 16 + lc8]));
        ldsm4(ql[kt], sptr(&sm.Ql[wq0 + lr][kt * 16 + lc8]));
    }

    const int g  = lane >> 2, tg = lane & 3;
    const int brow  = (lane & 7) + ((lane >> 3) & 1) * 8;
    const int bcol8 = (lane >> 4) * 8;

    float oacc[8][4];
#pragma unroll
    for (int i = 0; i < 8; i++)
#pragma unroll
        for (int j = 0; j < 4; j++) oacc[i][j] = 0.f;
    float m0 = -INFINITY, m1 = -INFINITY, l0 = 0.f, l1 = 0.f;

    const int kr = tid >> 2, kcb = (tid & 3) * 16;
    const __nv_bfloat16* gKh = g_Kth + ((size_t)bh * DKc + kr) * Sc;
    const __nv_bfloat16* gKl = g_Ktl + ((size_t)bh * DKc + kr) * Sc;

    const int* mr0base = mask + (size_t)(q0 + wq0 + g) * Sc + 2 * tg;

    for (int k0 = 0; k0 < Sc; k0 += 64) {
        cpasync16(&sm.Kh[kr][kcb],     gKh + k0 + kcb);
        cpasync16(&sm.Kh[kr][kcb + 8], gKh + k0 + kcb + 8);
        cpasync16(&sm.Kl[kr][kcb],     gKl + k0 + kcb);
        cpasync16(&sm.Kl[kr][kcb + 8], gKl + k0 + kcb + 8);
        {
            const __nv_bfloat16* gvh = g_Vh + (size_t)(rb + k0 + kr) * Dc + c0 + kcb;
            const __nv_bfloat16* gvl = g_Vl + (size_t)(rb + k0 + kr) * Dc + c0 + kcb;
            cpasync16(&sm.Vh[kr][kcb],     gvh);
            cpasync16(&sm.Vh[kr][kcb + 8], gvh + 8);
            cpasync16(&sm.Vl[kr][kcb],     gvl);
            cpasync16(&sm.Vl[kr][kcb + 8], gvl + 8);
        }
        cpcommit(); cpwait0();
        __syncthreads();

        float s[8][4];
#pragma unroll
        for (int i = 0; i < 8; i++)
#pragma unroll
            for (int j = 0; j < 4; j++) s[i][j] = 0.f;

#pragma unroll
        for (int kt = 0; kt < 4; kt++) {
#pragma unroll
            for (int p = 0; p < 4; p++) {
                uint32_t kbh[4], kbl[4];
                ldsm4t(kbh, sptr(&sm.Kh[kt * 16 + brow][p * 16 + bcol8]));
                ldsm4t(kbl, sptr(&sm.Kl[kt * 16 + brow][p * 16 + bcol8]));
                mma16816(s[2 * p],     qh[kt], kbh[0], kbh[1]);
                mma16816(s[2 * p],     qh[kt], kbl[0], kbl[1]);
                mma16816(s[2 * p],     ql[kt], kbh[0], kbh[1]);
                mma16816(s[2 * p + 1], qh[kt], kbh[2], kbh[3]);
                mma16816(s[2 * p + 1], qh[kt], kbl[2], kbl[3]);
                mma16816(s[2 * p + 1], ql[kt], kbh[2], kbh[3]);
            }
        }

        const int* mr0 = mr0base + k0;
        const int* mr1 = mr0 + 8 * Sc;
#pragma unroll
        for (int ni = 0; ni < 8; ni++) {
            int2 ma = *(const int2*)(mr0 + 8 * ni);
            int2 mb = *(const int2*)(mr1 + 8 * ni);
            s[ni][0] = ma.x ? s[ni][0] * 0.125f : -1e9f;
            s[ni][1] = ma.y ? s[ni][1] * 0.125f : -1e9f;
            s[ni][2] = mb.x ? s[ni][2] * 0.125f : -1e9f;
            s[ni][3] = mb.y ? s[ni][3] * 0.125f : -1e9f;
        }

        float mx0 = -INFINITY, mx1 = -INFINITY;
#pragma unroll
        for (int ni = 0; ni < 8; ni++) {
            mx0 = fmaxf(mx0, fmaxf(s[ni][0], s[ni][1]));
            mx1 = fmaxf(mx1, fmaxf(s[ni][2], s[ni][3]));
        }
        mx0 = fmaxf(mx0, __shfl_xor_sync(0xffffffffu, mx0, 1));
        mx0 = fmaxf(mx0, __shfl_xor_sync(0xffffffffu, mx0, 2));
        mx1 = fmaxf(mx1, __shfl_xor_sync(0xffffffffu, mx1, 1));
        mx1 = fmaxf(mx1, __shfl_xor_sync(0xffffffffu, mx1, 2));

        float mn0 = fmaxf(m0, mx0), mn1 = fmaxf(m1, mx1);
        float a0 = __expf(m0 - mn0), a1 = __expf(m1 - mn1);
        m0 = mn0; m1 = mn1;

        float sum0 = 0.f, sum1 = 0.f;
#pragma unroll
        for (int ni = 0; ni < 8; ni++) {
            s[ni][0] = __expf(s[ni][0] - mn0); sum0 += s[ni][0];
            s[ni][1] = __expf(s[ni][1] - mn0); sum0 += s[ni][1];
            s[ni][2] = __expf(s[ni][2] - mn1); sum1 += s[ni][2];
            s[ni][3] = __expf(s[ni][3] - mn1); sum1 += s[ni][3];
        }
        sum0 += __shfl_xor_sync(0xffffffffu, sum0, 1);
        sum0 += __shfl_xor_sync(0xffffffffu, sum0, 2);
        sum1 += __shfl_xor_sync(0xffffffffu, sum1, 1);
        sum1 += __shfl_xor_sync(0xffffffffu, sum1, 2);
        l0 = l0 * a0 + sum0;
        l1 = l1 * a1 + sum1;

#pragma unroll
        for (int ni = 0; ni < 8; ni++) {
            oacc[ni][0] *= a0; oacc[ni][1] *= a0;
            oacc[ni][2] *= a1; oacc[ni][3] *= a1;
        }

#pragma unroll
        for (int kt = 0; kt < 4; kt++) {
            uint32_t pah[4], pal[4];
            split2(s[2 * kt][0],     s[2 * kt][1],     pah[0], pal[0]);
            split2(s[2 * kt][2],     s[2 * kt][3],     pah[1], pal[1]);
            split2(s[2 * kt + 1][0], s[2 * kt + 1][1], pah[2], pal[2]);
            split2(s[2 * kt + 1][2], s[2 * kt + 1][3], pah[3], pal[3]);
#pragma unroll
            for (int p = 0; p < 4; p++) {
                uint32_t vbh[4], vbl[4];
                ldsm4t(vbh, sptr(&sm.Vh[kt * 16 + brow][p * 16 + bcol8]));
                ldsm4t(vbl, sptr(&sm.Vl[kt * 16 + brow][p * 16 + bcol8]));
                mma16816(oacc[2 * p],     pah, vbh[0], vbh[1]);
                mma16816(oacc[2 * p],     pah, vbl[0], vbl[1]);
                mma16816(oacc[2 * p],     pal, vbh[0], vbh[1]);
                mma16816(oacc[2 * p + 1], pah, vbh[2], vbh[3]);
                mma16816(oacc[2 * p + 1], pah, vbl[2], vbl[3]);
                mma16816(oacc[2 * p + 1], pal, vbh[2], vbh[3]);
            }
        }
        __syncthreads();
    }

    float i0 = 1.f / l0, i1 = 1.f / l1;
    const int r0 = rb + q0 + wq0 + g;
#pragma unroll
    for (int ni = 0; ni < 8; ni++) {
        int col = c0 + 8 * ni + 2 * tg;
        *(float2*)&ctx[(size_t)r0 * Dc + col] =
            make_float2(oacc[ni][0] * i0, oacc[ni][1] * i0);
        *(float2*)&ctx[(size_t)(r0 + 8) * Dc + col] =
            make_float2(oacc[ni][2] * i1, oacc[ni][3] * i1);
    }
}

// ---------------------------------------------------------------------------
// out = alpha * ((x+y) - mean) / (std_unbiased + eps) + beta, row of 768
// ---------------------------------------------------------------------------
__global__ __launch_bounds__(256)
void add_ln_kernel(const float* __restrict__ x, const float* __restrict__ y,
                   const float* __restrict__ alpha, const float* __restrict__ beta,
                   float* __restrict__ out)
{
    const int row = blockIdx.x;
    const int tid = threadIdx.x;
    const float* xr = x + (size_t)row * Dc;
    const float* yr = y + (size_t)row * Dc;

    __shared__ float red[8];
    __shared__ float sm_mean, sm_scale;

    float v[3];
    float s = 0.f;
#pragma unroll
    for (int t = 0; t < 3; t++) {
        v[t] = xr[tid + 256 * t] + yr[tid + 256 * t];
        s += v[t];
    }
#pragma unroll
    for (int o = 16; o > 0; o >>= 1) s += __shfl_xor_sync(0xFFFFFFFFu, s, o);
    if ((tid & 31) == 0) red[tid >> 5] = s;
    __syncthreads();
    if (tid == 0) {
        float tot = 0.f;
#pragma unroll
        for (int w = 0; w < 8; w++) tot += red[w];
        sm_mean = tot * (1.0f / (float)Dc);
    }
    __syncthreads();
    const float mean = sm_mean;

    float sq = 0.f;
#pragma unroll
    for (int t = 0; t < 3; t++) {
        float d = v[t] - mean;
        sq += d * d;
    }
#pragma unroll
    for (int o = 16; o > 0; o >>= 1) sq += __shfl_xor_sync(0xFFFFFFFFu, sq, o);
    if ((tid & 31) == 0) red[tid >> 5] = sq;
    __syncthreads();
    if (tid == 0) {
        float tot = 0.f;
#pragma unroll
        for (int w = 0; w < 8; w++) tot += red[w];
        float var = tot * (1.0f / (float)(Dc - 1));
        sm_scale = 1.0f / (sqrtf(var) + 1e-6f);
    }
    __syncthreads();

    const float sc = sm_scale * alpha[0];
    const float bt = beta[0];
#pragma unroll
    for (int t = 0; t < 3; t++)
        out[(size_t)row * Dc + tid + 256 * t] = (v[t] - mean) * sc + bt;
}

// ---------------------------------------------------------------------------
extern "C" void kernel_launch(void* const* d_in, const int* in_sizes, int n_in,
                              void* d_out, int out_size)
{
    const float* x      = (const float*)d_in[0];
    const float* wq     = (const float*)d_in[1];
    const float* bq     = (const float*)d_in[2];
    const float* wk     = (const float*)d_in[3];
    const float* bk     = (const float*)d_in[4];
    const float* wv     = (const float*)d_in[5];
    const float* bv     = (const float*)d_in[6];
    const float* wo     = (const float*)d_in[7];
    const float* bo     = (const float*)d_in[8];
    const float* w1     = (const float*)d_in[9];
    const float* b1     = (const float*)d_in[10];
    const float* w2     = (const float*)d_in[11];
    const float* b2     = (const float*)d_in[12];
    const float* alpha1 = (const float*)d_in[13];
    const float* beta1  = (const float*)d_in[14];
    const float* alpha2 = (const float*)d_in[15];
    const float* beta2  = (const float*)d_in[16];
    const int*   mask   = (const int*)d_in[17];

    float *k, *ctx, *tmp, *x1, *ff1;
    cudaGetSymbolAddress((void**)&k,   g_k);
    cudaGetSymbolAddress((void**)&ctx, g_ctx);
    cudaGetSymbolAddress((void**)&tmp, g_tmp);
    cudaGetSymbolAddress((void**)&x1,  g_x1);
    cudaGetSymbolAddress((void**)&ff1, g_ff1);

    __nv_bfloat16 *qh, *ql, *vh, *vl;
    cudaGetSymbolAddress((void**)&qh, g_Qh);
    cudaGetSymbolAddress((void**)&ql, g_Ql);
    cudaGetSymbolAddress((void**)&vh, g_Vh);
    cudaGetSymbolAddress((void**)&vl, g_Vl);

    int attn_smem = (int)sizeof(AttnSmem2);
    cudaFuncSetAttribute(attn_mma, cudaFuncAttributeMaxDynamicSharedMemorySize, attn_smem);

    dim3 blk(256);
    dim3 gD(Dc / 128, Mc / 128);     // (6, 32)
    dim3 gF(DFFc / 128, Mc / 128);   // (24, 32)

    // QKV projections: Q,K 3-term bf16 (feed softmax); V 2-term fp16
    mma_gemm3<1><<<gD, blk>>>(x, wq, bq, nullptr, qh, ql, Dc, Dc);
    mma_gemm3<0><<<gD, blk>>>(x, wk, bk, k, nullptr, nullptr, Dc, Dc);
    mma_gemm2<0, 1><<<gD, blk>>>(x, wv, bv, nullptr, vh, vl, Dc, Dc);

    // K transpose/split, then fused flash attention
    k_cvt<<<(Mc * Dc / 4 + 255) / 256, blk>>>(k);
    attn_mma<<<dim3(Sc / 128, Bc * Hc), blk, attn_smem>>>(mask, ctx);

    // O-projection (2-term), residual + LN1
    mma_gemm2<0, 0><<<gD, blk>>>(ctx, wo, bo, tmp, nullptr, nullptr, Dc, Dc);
    add_ln_kernel<<<Mc, blk>>>(x, tmp, alpha1, beta1, x1);

    // FFN (2-term both)
    mma_gemm2<1, 0><<<gF, blk>>>(x1, w1, b1, ff1, nullptr, nullptr, DFFc, Dc);
    mma_gemm2<0, 0><<<gD, blk>>>(ff1, w2, b2, tmp, nullptr, nullptr, Dc, DFFc);
    add_ln_kernel<<<Mc, blk>>>(x1, tmp, alpha2, beta2, (float*)d_out);
}

// round 8
// speedup vs baseline: 3.1749x; 1.1955x over previous
#include <cuda_runtime.h>
#include <cuda_fp16.h>
#include <stdint.h>
#include <math.h>

// Problem constants
static constexpr int Bc   = 2;
static constexpr int Sc   = 2048;
static constexpr int Dc   = 768;
static constexpr int Hc   = 12;
static constexpr int DKc  = 64;
static constexpr int DFFc = 3072;
static constexpr int Mc   = Bc * Sc;   // 4096 rows

// f32 scratch
__device__ float g_tmp[Mc * Dc];
__device__ float g_x1 [Mc * Dc];

// fp16 hi/lo activations
__device__ __half g_xh  [Mc * Dc],   g_xl  [Mc * Dc];
__device__ __half g_qh  [Mc * Dc],   g_ql  [Mc * Dc];
__device__ __half g_kh  [Mc * Dc],   g_kl  [Mc * Dc];
__device__ __half g_vh  [Mc * Dc];
__device__ __half g_ctxh[Mc * Dc],   g_ctxl[Mc * Dc];
__device__ __half g_x1h [Mc * Dc],   g_x1l [Mc * Dc];
__device__ __half g_ff1h[Mc * DFFc], g_ff1l[Mc * DFFc];

// fp16 weights ([K][N] layout preserved)
__device__ __half g_wqh[Dc * Dc],   g_wql[Dc * Dc];
__device__ __half g_wkh[Dc * Dc],   g_wkl[Dc * Dc];
__device__ __half g_wvh[Dc * Dc];
__device__ __half g_woh[Dc * Dc];
__device__ __half g_w1h[Dc * DFFc];
__device__ __half g_w2h[DFFc * Dc];

// ---------------------------------------------------------------------------
// helpers
// ---------------------------------------------------------------------------
__device__ __forceinline__ uint32_t sptr(const void* p) {
    return (uint32_t)__cvta_generic_to_shared(p);
}
__device__ __forceinline__ void ldsm4(uint32_t r[4], uint32_t addr) {
    asm volatile("ldmatrix.sync.aligned.m8n8.x4.shared.b16 {%0,%1,%2,%3},[%4];"
                 : "=r"(r[0]), "=r"(r[1]), "=r"(r[2]), "=r"(r[3]) : "r"(addr));
}
__device__ __forceinline__ void ldsm4t(uint32_t r[4], uint32_t addr) {
    asm volatile("ldmatrix.sync.aligned.m8n8.x4.trans.shared.b16 {%0,%1,%2,%3},[%4];"
                 : "=r"(r[0]), "=r"(r[1]), "=r"(r[2]), "=r"(r[3]) : "r"(addr));
}
__device__ __forceinline__ void mma16816h(float c[4], const uint32_t a[4],
                                          uint32_t b0, uint32_t b1) {
    asm volatile(
        "mma.sync.aligned.m16n8k16.row.col.f32.f16.f16.f32 "
        "{%0,%1,%2,%3},{%4,%5,%6,%7},{%8,%9},{%0,%1,%2,%3};"
        : "+f"(c[0]), "+f"(c[1]), "+f"(c[2]), "+f"(c[3])
        : "r"(a[0]), "r"(a[1]), "r"(a[2]), "r"(a[3]), "r"(b0), "r"(b1));
}
__device__ __forceinline__ void split2h(float a, float b, uint32_t& h, uint32_t& l) {
    __half ha = __float2half_rn(a), hb = __float2half_rn(b);
    __half2 H; H.x = ha; H.y = hb;
    __half2 L; L.x = __float2half_rn(a - __half2float(ha));
    L.y = __float2half_rn(b - __half2float(hb));
    h = *(uint32_t*)&H;
    l = *(uint32_t*)&L;
}
__device__ __forceinline__ void pack2h(float a, float b, uint32_t& h) {
    __half2 H; H.x = __float2half_rn(a); H.y = __float2half_rn(b);
    h = *(uint32_t*)&H;
}
__device__ __forceinline__ void cpasync16(const void* smem, const void* gmem) {
    asm volatile("cp.async.cg.shared.global [%0],[%1],16;"
                 :: "r"(sptr(smem)), "l"(gmem));
}
__device__ __forceinline__ void cpcommit() { asm volatile("cp.async.commit_group;"); }
template<int N>
__device__ __forceinline__ void cpwait() {
    asm volatile("cp.async.wait_group %0;" :: "n"(N));
}

// ---------------------------------------------------------------------------
// conversion kernels (once per launch)
// ---------------------------------------------------------------------------
__global__ __launch_bounds__(256)
void cvt_hl(const float* __restrict__ src, __half* __restrict__ h,
            __half* __restrict__ l)
{
    size_t i4 = ((size_t)blockIdx.x * 256 + threadIdx.x) * 4;
    float4 f = *(const float4*)(src + i4);
    float v[4] = {f.x, f.y, f.z, f.w};
    __half hh[4], ll[4];
#pragma unroll
    for (int i = 0; i < 4; i++) {
        hh[i] = __float2half_rn(v[i]);
        ll[i] = __float2half_rn(v[i] - __half2float(hh[i]));
    }
    *(uint2*)(h + i4) = *(uint2*)hh;
    *(uint2*)(l + i4) = *(uint2*)ll;
}
__global__ __launch_bounds__(256)
void cvt_h(const float* __restrict__ src, __half* __restrict__ h)
{
    size_t i4 = ((size_t)blockIdx.x * 256 + threadIdx.x) * 4;
    float4 f = *(const float4*)(src + i4);
    __half hh[4] = {__float2half_rn(f.x), __float2half_rn(f.y),
                    __float2half_rn(f.z), __float2half_rn(f.w)};
    *(uint2*)(h + i4) = *(uint2*)hh;
}

// ---------------------------------------------------------------------------
// fp16 tensor GEMM with pre-split operands. C = (Ah+Al) @ (Wh[+Wl]) + bias
// TERMS: 2 => AhWh+AlWh;  3 => AhWh+AlWh+AhWl
// EMIT:  0 => f32 Cf;  1 => fp16 h/l Ch,Cl;  2 => fp16 h only
// Tile 128x128, BK=32, 8 warps, double-buffered cp.async.
// ---------------------------------------------------------------------------
#define HG_ASZ   (128 * 40)   /* halves per A tile (padded) */
#define HG_WSZ   (32 * 136)   /* halves per W tile (padded) */
#define HG_BUF(TERMS)   (2 * HG_ASZ + ((TERMS) - 1) * HG_WSZ)
#define HG_SMEM(TERMS)  (2 * HG_BUF(TERMS) * 2)

template<int TERMS, int RELU, int EMIT>
__global__ __launch_bounds__(256)
void hgemm(const __half* __restrict__ Ah_g, const __half* __restrict__ Al_g,
           const __half* __restrict__ Wh_g, const __half* __restrict__ Wl_g,
           const float* __restrict__ bias,
           float* __restrict__ Cf, __half* __restrict__ Ch, __half* __restrict__ Cl,
           int Ndim, int Kdim)
{
    extern __shared__ __half sh[];
    const int tid  = threadIdx.x;
    const int lane = tid & 31;
    const int wid  = tid >> 5;
    const int wm   = (wid & 1) * 64;
    const int wn   = (wid >> 1) * 32;
    const int bM   = blockIdx.y * 128;
    const int bN   = blockIdx.x * 128;

    // staging roles
    const int ar = tid >> 1, ac = (tid & 1) * 16;   // A: 2 thr/row, 16 halves each
    const int wr = tid >> 3, wc = (tid & 7) * 16;   // W: 8 thr/row, 16 halves each

    const __half* gAh = Ah_g + (size_t)(bM + ar) * Kdim + ac;
    const __half* gAl = Al_g + (size_t)(bM + ar) * Kdim + ac;
    const __half* gWh = Wh_g + (size_t)wr * Ndim + bN + wc;
    const __half* gWl = (TERMS == 3) ? (Wl_g + (size_t)wr * Ndim + bN + wc) : nullptr;
    const size_t WkS = (size_t)32 * Ndim;

    const int BUF = HG_BUF(TERMS);

    auto stage = [&](int b, int k0) {
        __half* pAh = sh + b * BUF;
        __half* pAl = pAh + HG_ASZ;
        __half* pWh = pAl + HG_ASZ;
        cpasync16(pAh + ar * 40 + ac,     gAh + k0);
        cpasync16(pAh + ar * 40 + ac + 8, gAh + k0 + 8);
        cpasync16(pAl + ar * 40 + ac,     gAl + k0);
        cpasync16(pAl + ar * 40 + ac + 8, gAl + k0 + 8);
        cpasync16(pWh + wr * 136 + wc,     gWh + (size_t)(k0 / 32) * WkS);
        cpasync16(pWh + wr * 136 + wc + 8, gWh + (size_t)(k0 / 32) * WkS + 8);
        if (TERMS == 3) {
            __half* pWl = pWh + HG_WSZ;
            cpasync16(pWl + wr * 136 + wc,     gWl + (size_t)(k0 / 32) * WkS);
            cpasync16(pWl + wr * 136 + wc + 8, gWl + (size_t)(k0 / 32) * WkS + 8);
        }
        cpcommit();
    };

    float acc[4][4][4];
#pragma unroll
    for (int a = 0; a < 4; a++)
#pragma unroll
        for (int b = 0; b < 4; b++)
#pragma unroll
            for (int c = 0; c < 4; c++) acc[a][b][c] = 0.f;

    const int lr    = lane & 15;
    const int lc8   = (lane >> 4) * 8;
    const int brow  = (lane & 7) + ((lane >> 3) & 1) * 8;
    const int bcol8 = (lane >> 4) * 8;

    const int T = Kdim / 32;
    stage(0, 0);

    for (int t = 0; t < T; t++) {
        const int b = t & 1;
        if (t + 1 < T) { stage((t + 1) & 1, (t + 1) * 32); cpwait<1>(); }
        else           { cpwait<0>(); }
        __syncthreads();

        __half* pAh = sh + b * BUF;
        __half* pAl = pAh + HG_ASZ;
        __half* pWh = pAl + HG_ASZ;
        __half* pWl = pWh + HG_WSZ;

#pragma unroll
        for (int ks = 0; ks < 32; ks += 16) {
            uint32_t ah[4][4], al[4][4];
#pragma unroll
            for (int mi = 0; mi < 4; mi++) {
                ldsm4(ah[mi], sptr(pAh + (wm + mi * 16 + lr) * 40 + ks + lc8));
                ldsm4(al[mi], sptr(pAl + (wm + mi * 16 + lr) * 40 + ks + lc8));
            }
#pragma unroll
            for (int p = 0; p < 2; p++) {
                uint32_t bh[4];
                ldsm4t(bh, sptr(pWh + (ks + brow) * 136 + wn + p * 16 + bcol8));
                uint32_t bl[4];
                if (TERMS == 3)
                    ldsm4t(bl, sptr(pWl + (ks + brow) * 136 + wn + p * 16 + bcol8));
#pragma unroll
                for (int s = 0; s < 2; s++) {
                    const int ni = p * 2 + s;
#pragma unroll
                    for (int mi = 0; mi < 4; mi++) {
                        mma16816h(acc[mi][ni], ah[mi], bh[s * 2], bh[s * 2 + 1]);
                        mma16816h(acc[mi][ni], al[mi], bh[s * 2], bh[s * 2 + 1]);
                        if (TERMS == 3)
                            mma16816h(acc[mi][ni], ah[mi], bl[s * 2], bl[s * 2 + 1]);
                    }
                }
            }
        }
        __syncthreads();
    }

    const int gr = lane >> 2, gc = (lane & 3) * 2;
#pragma unroll
    for (int mi = 0; mi < 4; mi++) {
#pragma unroll
        for (int ni = 0; ni < 4; ni++) {
            int row = bM + wm + mi * 16 + gr;
            int col = bN + wn + ni * 8 + gc;
            float b0 = bias[col], b1 = bias[col + 1];
            float v0 = acc[mi][ni][0] + b0, v1 = acc[mi][ni][1] + b1;
            float v2 = acc[mi][ni][2] + b0, v3 = acc[mi][ni][3] + b1;
            if (RELU) {
                v0 = fmaxf(v0, 0.f); v1 = fmaxf(v1, 0.f);
                v2 = fmaxf(v2, 0.f); v3 = fmaxf(v3, 0.f);
            }
            if (EMIT == 0) {
                *(float2*)&Cf[(size_t)row * Ndim + col]       = make_float2(v0, v1);
                *(float2*)&Cf[(size_t)(row + 8) * Ndim + col] = make_float2(v2, v3);
            } else if (EMIT == 1) {
                uint32_t h0, l0, h1, l1;
                split2h(v0, v1, h0, l0);
                split2h(v2, v3, h1, l1);
                *(uint32_t*)&Ch[(size_t)row * Ndim + col]       = h0;
                *(uint32_t*)&Cl[(size_t)row * Ndim + col]       = l0;
                *(uint32_t*)&Ch[(size_t)(row + 8) * Ndim + col] = h1;
                *(uint32_t*)&Cl[(size_t)(row + 8) * Ndim + col] = l1;
            } else {
                uint32_t h0, h1;
                pack2h(v0, v1, h0);
                pack2h(v2, v3, h1);
                *(uint32_t*)&Ch[(size_t)row * Ndim + col]       = h0;
                *(uint32_t*)&Ch[(size_t)(row + 8) * Ndim + col] = h1;
            }
        }
    }
}

// ---------------------------------------------------------------------------
// fp16 flash attention. QT=128, KT=64. QK^T 3-term (q h/l, k h/l via
// non-trans ldmatrix on natural [s][d] layout); PV 2-term (P h/l x Vh).
// ---------------------------------------------------------------------------
struct AttnSmem3 {
    __half Qh[128][72], Ql[128][72];
    __half Kh[64][72],  Kl[64][72];
    __half Vh[64][72];
};

__global__ __launch_bounds__(256, 2)
void attn_mma(const int* __restrict__ mask)
{
    extern __shared__ char sraw[];
    AttnSmem3& sm = *reinterpret_cast<AttnSmem3*>(sraw);

    const int tid = threadIdx.x, lane = tid & 31, wid = tid >> 5;
    const int qb = blockIdx.x, bh = blockIdx.y;
    const int b = bh / Hc, h = bh - b * Hc;
    const int q0 = qb * 128, rb = b * Sc, c0 = h * DKc;

    // stage Q tile
    {
        int r = tid >> 1, cb = (tid & 1) * 32;
        const __half* gq_h = g_qh + (size_t)(rb + q0 + r) * Dc + c0 + cb;
        const __half* gq_l = g_ql + (size_t)(rb + q0 + r) * Dc + c0 + cb;
#pragma unroll
        for (int j = 0; j < 4; j++) {
            cpasync16(&sm.Qh[r][cb + j * 8], gq_h + j * 8);
            cpasync16(&sm.Ql[r][cb + j * 8], gq_l + j * 8);
        }
        cpcommit(); cpwait<0>();
    }
    __syncthreads();

    const int lr = lane & 15, lc8 = (lane >> 4) * 8;
    const int wq0 = wid * 16;
    uint32_t qh[4][4], ql[4][4];
#pragma unroll
    for (int kt = 0; kt < 4; kt++) {
        ldsm4(qh[kt], sptr(&sm.Qh[wq0 + lr][kt * 16 + lc8]));
        ldsm4(ql[kt], sptr(&sm.Ql[wq0 + lr][kt * 16 + lc8]));
    }

    const int g  = lane >> 2, tg = lane & 3;
    // non-trans B-fragment addressing for K (rows = kseq, cols = d)
    const int krow  = (lane & 7) + ((lane >> 4) << 3);
    const int kcol  = ((lane >> 3) & 1) * 8;
    // trans B-fragment addressing for V (rows = kseq, cols = d)
    const int brow  = (lane & 7) + ((lane >> 3) & 1) * 8;
    const int bcol8 = (lane >> 4) * 8;

    float oacc[8][4];
#pragma unroll
    for (int i = 0; i < 8; i++)
#pragma unroll
        for (int j = 0; j < 4; j++) oacc[i][j] = 0.f;
    float m0 = -INFINITY, m1 = -INFINITY, l0 = 0.f, l1 = 0.f;

    // K/V staging roles: 64 rows, 4 thr/row, 16 halves each
    const int kr = tid >> 2, kcb = (tid & 3) * 16;
    const __half* gK_h = g_kh + (size_t)(rb + kr) * Dc + c0 + kcb;
    const __half* gK_l = g_kl + (size_t)(rb + kr) * Dc + c0 + kcb;
    const __half* gV_h = g_vh + (size_t)(rb + kr) * Dc + c0 + kcb;

    const int* mr0base = mask + (size_t)(q0 + wq0 + g) * Sc + 2 * tg;

    for (int k0 = 0; k0 < Sc; k0 += 64) {
        const size_t go = (size_t)k0 * Dc;
        cpasync16(&sm.Kh[kr][kcb],     gK_h + go);
        cpasync16(&sm.Kh[kr][kcb + 8], gK_h + go + 8);
        cpasync16(&sm.Kl[kr][kcb],     gK_l + go);
        cpasync16(&sm.Kl[kr][kcb + 8], gK_l + go + 8);
        cpasync16(&sm.Vh[kr][kcb],     gV_h + go);
        cpasync16(&sm.Vh[kr][kcb + 8], gV_h + go + 8);
        cpcommit(); cpwait<0>();
        __syncthreads();

        // ---- S = Q K^T (3-term fp16) ----
        float s[8][4];
#pragma unroll
        for (int i = 0; i < 8; i++)
#pragma unroll
            for (int j = 0; j < 4; j++) s[i][j] = 0.f;

#pragma unroll
        for (int kt = 0; kt < 4; kt++) {
#pragma unroll
            for (int p = 0; p < 4; p++) {
                uint32_t kbh[4], kbl[4];
                ldsm4(kbh, sptr(&sm.Kh[p * 16 + krow][kt * 16 + kcol]));
                ldsm4(kbl, sptr(&sm.Kl[p * 16 + krow][kt * 16 + kcol]));
                mma16816h(s[2 * p],     qh[kt], kbh[0], kbh[1]);
                mma16816h(s[2 * p],     ql[kt], kbh[0], kbh[1]);
                mma16816h(s[2 * p],     qh[kt], kbl[0], kbl[1]);
                mma16816h(s[2 * p + 1], qh[kt], kbh[2], kbh[3]);
                mma16816h(s[2 * p + 1], ql[kt], kbh[2], kbh[3]);
                mma16816h(s[2 * p + 1], qh[kt], kbl[2], kbl[3]);
            }
        }

        // ---- scale + mask ----
        const int* mr0 = mr0base + k0;
        const int* mr1 = mr0 + 8 * Sc;
#pragma unroll
        for (int ni = 0; ni < 8; ni++) {
            int2 ma = *(const int2*)(mr0 + 8 * ni);
            int2 mb = *(const int2*)(mr1 + 8 * ni);
            s[ni][0] = ma.x ? s[ni][0] * 0.125f : -1e9f;
            s[ni][1] = ma.y ? s[ni][1] * 0.125f : -1e9f;
            s[ni][2] = mb.x ? s[ni][2] * 0.125f : -1e9f;
            s[ni][3] = mb.y ? s[ni][3] * 0.125f : -1e9f;
        }

        // ---- online softmax ----
        float mx0 = -INFINITY, mx1 = -INFINITY;
#pragma unroll
        for (int ni = 0; ni < 8; ni++) {
            mx0 = fmaxf(mx0, fmaxf(s[ni][0], s[ni][1]));
            mx1 = fmaxf(mx1, fmaxf(s[ni][2], s[ni][3]));
        }
        mx0 = fmaxf(mx0, __shfl_xor_sync(0xffffffffu, mx0, 1));
        mx0 = fmaxf(mx0, __shfl_xor_sync(0xffffffffu, mx0, 2));
        mx1 = fmaxf(mx1, __shfl_xor_sync(0xffffffffu, mx1, 1));
        mx1 = fmaxf(mx1, __shfl_xor_sync(0xffffffffu, mx1, 2));

        float mn0 = fmaxf(m0, mx0), mn1 = fmaxf(m1, mx1);
        float a0 = __expf(m0 - mn0), a1 = __expf(m1 - mn1);
        m0 = mn0; m1 = mn1;

        float sum0 = 0.f, sum1 = 0.f;
#pragma unroll
        for (int ni = 0; ni < 8; ni++) {
            s[ni][0] = __expf(s[ni][0] - mn0); sum0 += s[ni][0];
            s[ni][1] = __expf(s[ni][1] - mn0); sum0 += s[ni][1];
            s[ni][2] = __expf(s[ni][2] - mn1); sum1 += s[ni][2];
            s[ni][3] = __expf(s[ni][3] - mn1); sum1 += s[ni][3];
        }
        sum0 += __shfl_xor_sync(0xffffffffu, sum0, 1);
        sum0 += __shfl_xor_sync(0xffffffffu, sum0, 2);
        sum1 += __shfl_xor_sync(0xffffffffu, sum1, 1);
        sum1 += __shfl_xor_sync(0xffffffffu, sum1, 2);
        l0 = l0 * a0 + sum0;
        l1 = l1 * a1 + sum1;

#pragma unroll
        for (int ni = 0; ni < 8; ni++) {
            oacc[ni][0] *= a0; oacc[ni][1] *= a0;
            oacc[ni][2] *= a1; oacc[ni][3] *= a1;
        }

        // ---- O += P @ V (2-term fp16) ----
#pragma unroll
        for (int kt = 0; kt < 4; kt++) {
            uint32_t pah[4], pal[4];
            split2h(s[2 * kt][0],     s[2 * kt][1],     pah[0], pal[0]);
            split2h(s[2 * kt][2],     s[2 * kt][3],     pah[1], pal[1]);
            split2h(s[2 * kt + 1][0], s[2 * kt + 1][1], pah[2], pal[2]);
            split2h(s[2 * kt + 1][2], s[2 * kt + 1][3], pah[3], pal[3]);
#pragma unroll
            for (int p = 0; p < 4; p++) {
                uint32_t vbh[4];
                ldsm4t(vbh, sptr(&sm.Vh[kt * 16 + brow][p * 16 + bcol8]));
                mma16816h(oacc[2 * p],     pah, vbh[0], vbh[1]);
                mma16816h(oacc[2 * p],     pal, vbh[0], vbh[1]);
                mma16816h(oacc[2 * p + 1], pah, vbh[2], vbh[3]);
                mma16816h(oacc[2 * p + 1], pal, vbh[2], vbh[3]);
            }
        }
        __syncthreads();
    }

    // epilogue: emit ctx as fp16 h/l
    float i0 = 1.f / l0, i1 = 1.f / l1;
    const int r0 = rb + q0 + wq0 + g;
#pragma unroll
    for (int ni = 0; ni < 8; ni++) {
        int col = c0 + 8 * ni + 2 * tg;
        uint32_t h0, ll0, h1, ll1;
        split2h(oacc[ni][0] * i0, oacc[ni][1] * i0, h0, ll0);
        split2h(oacc[ni][2] * i1, oacc[ni][3] * i1, h1, ll1);
        *(uint32_t*)&g_ctxh[(size_t)r0 * Dc + col]       = h0;
        *(uint32_t*)&g_ctxl[(size_t)r0 * Dc + col]       = ll0;
        *(uint32_t*)&g_ctxh[(size_t)(r0 + 8) * Dc + col] = h1;
        *(uint32_t*)&g_ctxl[(size_t)(r0 + 8) * Dc + col] = ll1;
    }
}

// ---------------------------------------------------------------------------
// add + layernorm; EMIT_HL: also emit fp16 h/l of the output
// ---------------------------------------------------------------------------
template<int EMIT_HL>
__global__ __launch_bounds__(256)
void add_ln_kernel(const float* __restrict__ x, const float* __restrict__ y,
                   const float* __restrict__ alpha, const float* __restrict__ beta,
                   float* __restrict__ out,
                   __half* __restrict__ oh, __half* __restrict__ ol)
{
    const int row = blockIdx.x;
    const int tid = threadIdx.x;
    const float* xr = x + (size_t)row * Dc;
    const float* yr = y + (size_t)row * Dc;

    __shared__ float red[8];
    __shared__ float sm_mean, sm_scale;

    float v[3];
    float s = 0.f;
#pragma unroll
    for (int t = 0; t < 3; t++) {
        v[t] = xr[tid + 256 * t] + yr[tid + 256 * t];
        s += v[t];
    }
#pragma unroll
    for (int o = 16; o > 0; o >>= 1) s += __shfl_xor_sync(0xFFFFFFFFu, s, o);
    if ((tid & 31) == 0) red[tid >> 5] = s;
    __syncthreads();
    if (tid == 0) {
        float tot = 0.f;
#pragma unroll
        for (int w = 0; w < 8; w++) tot += red[w];
        sm_mean = tot * (1.0f / (float)Dc);
    }
    __syncthreads();
    const float mean = sm_mean;

    float sq = 0.f;
#pragma unroll
    for (int t = 0; t < 3; t++) {
        float d = v[t] - mean;
        sq += d * d;
    }
#pragma unroll
    for (int o = 16; o > 0; o >>= 1) sq += __shfl_xor_sync(0xFFFFFFFFu, sq, o);
    if ((tid & 31) == 0) red[tid >> 5] = sq;
    __syncthreads();
    if (tid == 0) {
        float tot = 0.f;
#pragma unroll
        for (int w = 0; w < 8; w++) tot += red[w];
        float var = tot * (1.0f / (float)(Dc - 1));
        sm_scale = 1.0f / (sqrtf(var) + 1e-6f);
    }
    __syncthreads();

    const float sc = sm_scale * alpha[0];
    const float bt = beta[0];
#pragma unroll
    for (int t = 0; t < 3; t++) {
        float o = (v[t] - mean) * sc + bt;
        out[(size_t)row * Dc + tid + 256 * t] = o;
        if (EMIT_HL) {
            __half h = __float2half_rn(o);
            oh[(size_t)row * Dc + tid + 256 * t] = h;
            ol[(size_t)row * Dc + tid + 256 * t] =
                __float2half_rn(o - __half2float(h));
        }
    }
}

// ---------------------------------------------------------------------------
extern "C" void kernel_launch(void* const* d_in, const int* in_sizes, int n_in,
                              void* d_out, int out_size)
{
    const float* x      = (const float*)d_in[0];
    const float* wq     = (const float*)d_in[1];
    const float* bq     = (const float*)d_in[2];
    const float* wk     = (const float*)d_in[3];
    const float* bk     = (const float*)d_in[4];
    const float* wv     = (const float*)d_in[5];
    const float* bv     = (const float*)d_in[6];
    const float* wo     = (const float*)d_in[7];
    const float* bo     = (const float*)d_in[8];
    const float* w1     = (const float*)d_in[9];
    const float* b1     = (const float*)d_in[10];
    const float* w2     = (const float*)d_in[11];
    const float* b2     = (const float*)d_in[12];
    const float* alpha1 = (const float*)d_in[13];
    const float* beta1  = (const float*)d_in[14];
    const float* alpha2 = (const float*)d_in[15];
    const float* beta2  = (const float*)d_in[16];
    const int*   mask   = (const int*)d_in[17];

    float *tmp, *x1;
    cudaGetSymbolAddress((void**)&tmp, g_tmp);
    cudaGetSymbolAddress((void**)&x1,  g_x1);

    __half *xh, *xl, *qh, *ql, *kh, *kl, *vh, *ctxh, *ctxl, *x1h, *x1l, *ff1h, *ff1l;
    cudaGetSymbolAddress((void**)&xh,   g_xh);
    cudaGetSymbolAddress((void**)&xl,   g_xl);
    cudaGetSymbolAddress((void**)&qh,   g_qh);
    cudaGetSymbolAddress((void**)&ql,   g_ql);
    cudaGetSymbolAddress((void**)&kh,   g_kh);
    cudaGetSymbolAddress((void**)&kl,   g_kl);
    cudaGetSymbolAddress((void**)&vh,   g_vh);
    cudaGetSymbolAddress((void**)&ctxh, g_ctxh);
    cudaGetSymbolAddress((void**)&ctxl, g_ctxl);
    cudaGetSymbolAddress((void**)&x1h,  g_x1h);
    cudaGetSymbolAddress((void**)&x1l,  g_x1l);
    cudaGetSymbolAddress((void**)&ff1h, g_ff1h);
    cudaGetSymbolAddress((void**)&ff1l, g_ff1l);

    __half *wqh, *wql, *wkh, *wkl, *wvh, *woh, *w1h, *w2h;
    cudaGetSymbolAddress((void**)&wqh, g_wqh);
    cudaGetSymbolAddress((void**)&wql, g_wql);
    cudaGetSymbolAddress((void**)&wkh, g_wkh);
    cudaGetSymbolAddress((void**)&wkl, g_wkl);
    cudaGetSymbolAddress((void**)&wvh, g_wvh);
    cudaGetSymbolAddress((void**)&woh, g_woh);
    cudaGetSymbolAddress((void**)&w1h, g_w1h);
    cudaGetSymbolAddress((void**)&w2h, g_w2h);

    int attn_smem = (int)sizeof(AttnSmem3);
    cudaFuncSetAttribute(attn_mma, cudaFuncAttributeMaxDynamicSharedMemorySize, attn_smem);
    cudaFuncSetAttribute(hgemm<3, 0, 1>, cudaFuncAttributeMaxDynamicSharedMemorySize,
                         HG_SMEM(3));
    cudaFuncSetAttribute(hgemm<2, 0, 2>, cudaFuncAttributeMaxDynamicSharedMemorySize,
                         HG_SMEM(2));
    cudaFuncSetAttribute(hgemm<2, 0, 0>, cudaFuncAttributeMaxDynamicSharedMemorySize,
                         HG_SMEM(2));
    cudaFuncSetAttribute(hgemm<2, 1, 1>, cudaFuncAttributeMaxDynamicSharedMemorySize,
                         HG_SMEM(2));

    dim3 blk(256);
    dim3 gD(Dc / 128, Mc / 128);     // (6, 32)
    dim3 gF(DFFc / 128, Mc / 128);   // (24, 32)

    // 1. weight + input conversions
    cvt_hl<<<Dc * Dc / 1024, blk>>>(wq, wqh, wql);
    cvt_hl<<<Dc * Dc / 1024, blk>>>(wk, wkh, wkl);
    cvt_h <<<Dc * Dc / 1024, blk>>>(wv, wvh);
    cvt_h <<<Dc * Dc / 1024, blk>>>(wo, woh);
    cvt_h <<<Dc * DFFc / 1024, blk>>>(w1, w1h);
    cvt_h <<<DFFc * Dc / 1024, blk>>>(w2, w2h);
    cvt_hl<<<(int)((size_t)Mc * Dc / 1024), blk>>>(x, xh, xl);

    // 2. QKV projections
    hgemm<3, 0, 1><<<gD, blk, HG_SMEM(3)>>>(xh, xl, wqh, wql, bq,
                                            nullptr, qh, ql, Dc, Dc);
    hgemm<3, 0, 1><<<gD, blk, HG_SMEM(3)>>>(xh, xl, wkh, wkl, bk,
                                            nullptr, kh, kl, Dc, Dc);
    hgemm<2, 0, 2><<<gD, blk, HG_SMEM(2)>>>(xh, xl, wvh, nullptr, bv,
                                            nullptr, vh, nullptr, Dc, Dc);

    // 3. flash attention
    attn_mma<<<dim3(Sc / 128, Bc * Hc), blk, attn_smem>>>(mask);

    // 4. O-projection + LN1
    hgemm<2, 0, 0><<<gD, blk, HG_SMEM(2)>>>(ctxh, ctxl, woh, nullptr, bo,
                                            tmp, nullptr, nullptr, Dc, Dc);
    add_ln_kernel<1><<<Mc, blk>>>(x, tmp, alpha1, beta1, x1, x1h, x1l);

    // 5. FFN
    hgemm<2, 1, 1><<<gF, blk, HG_SMEM(2)>>>(x1h, x1l, w1h, nullptr, b1,
                                            nullptr, ff1h, ff1l, DFFc, Dc);
    hgemm<2, 0, 0><<<gD, blk, HG_SMEM(2)>>>(ff1h, ff1l, w2h, nullptr, b2,
                                            tmp, nullptr, nullptr, Dc, DFFc);
    add_ln_kernel<0><<<Mc, blk>>>(x1, tmp, alpha2, beta2, (float*)d_out,
                                  nullptr, nullptr);
}